// round 1
// baseline (speedup 1.0000x reference)
#include <cuda_runtime.h>
#include <math.h>

#define T_SEQ 2048
#define N_EMBD 2048
#define N_HEADS 16
#define N_GROUPS 4
#define HEAD_SIZE 128
#define INTER 5632
#define VOCAB 32000
#define QKV_DIM 3072   // (16 + 2*4) * 128

// ---------------- scratch (static device globals; no runtime allocation) ----
__device__ float g_x  [T_SEQ * N_EMBD];
__device__ float g_n  [T_SEQ * N_EMBD];
__device__ float g_qkv[T_SEQ * QKV_DIM];
__device__ float g_q  [N_HEADS  * T_SEQ * HEAD_SIZE];
__device__ float g_k  [N_GROUPS * T_SEQ * HEAD_SIZE];
__device__ float g_vT [N_GROUPS * HEAD_SIZE * T_SEQ];
__device__ float g_S  [N_HEADS * T_SEQ * T_SEQ];      // 256 MB scores
__device__ float g_y  [T_SEQ * N_EMBD];
__device__ float g_h1 [T_SEQ * INTER];
__device__ float g_h2 [T_SEQ * INTER];

// ---------------- generic NT GEMM: C[m,n] = sum_k A[m,k]*B[n,k] (+add) ------
#define BM 128
#define BN 128
#define BK 8
#define TM 8
#define TN 8

__global__ void __launch_bounds__(256)
gemm_nt(const float* __restrict__ A, int lda, long long strideA,
        const float* __restrict__ B, int ldb, long long strideB, int bdiv,
        float* __restrict__ C, int ldc, long long strideC,
        const float* __restrict__ addC, long long strideAdd,
        int K)
{
    int z = blockIdx.z;
    A += (long long)z * strideA;
    B += (long long)(z / bdiv) * strideB;
    C += (long long)z * strideC;
    if (addC) addC += (long long)z * strideAdd;

    __shared__ float As[BK][BM];
    __shared__ float Bs[BK][BN];

    int tid = threadIdx.x;
    int m0 = blockIdx.y * BM;
    int n0 = blockIdx.x * BN;

    // each thread loads one float4 of A and one of B per BK step
    int a_row  = tid >> 1;          // 0..127
    int a_col4 = (tid & 1) * 4;     // 0 or 4

    int tx = tid & 15;              // 0..15
    int ty = tid >> 4;              // 0..15

    const float* Aptr = A + (long long)(m0 + a_row) * lda + a_col4;
    const float* Bptr = B + (long long)(n0 + a_row) * ldb + a_col4;

    float acc[TM][TN];
    #pragma unroll
    for (int i = 0; i < TM; i++)
        #pragma unroll
        for (int j = 0; j < TN; j++) acc[i][j] = 0.f;

    for (int k0 = 0; k0 < K; k0 += BK) {
        float4 av = *(const float4*)Aptr;
        float4 bv = *(const float4*)Bptr;
        As[a_col4+0][a_row] = av.x; As[a_col4+1][a_row] = av.y;
        As[a_col4+2][a_row] = av.z; As[a_col4+3][a_row] = av.w;
        Bs[a_col4+0][a_row] = bv.x; Bs[a_col4+1][a_row] = bv.y;
        Bs[a_col4+2][a_row] = bv.z; Bs[a_col4+3][a_row] = bv.w;
        __syncthreads();

        #pragma unroll
        for (int kk = 0; kk < BK; kk++) {
            float4 a0 = *(const float4*)&As[kk][ty*TM];
            float4 a1 = *(const float4*)&As[kk][ty*TM + 4];
            float4 b0 = *(const float4*)&Bs[kk][tx*TN];
            float4 b1 = *(const float4*)&Bs[kk][tx*TN + 4];
            float ra[TM] = {a0.x,a0.y,a0.z,a0.w,a1.x,a1.y,a1.z,a1.w};
            float rb[TN] = {b0.x,b0.y,b0.z,b0.w,b1.x,b1.y,b1.z,b1.w};
            #pragma unroll
            for (int i = 0; i < TM; i++)
                #pragma unroll
                for (int j = 0; j < TN; j++)
                    acc[i][j] = fmaf(ra[i], rb[j], acc[i][j]);
        }
        __syncthreads();
        Aptr += BK; Bptr += BK;
    }

    #pragma unroll
    for (int i = 0; i < TM; i++) {
        long long m = m0 + ty*TM + i;
        #pragma unroll
        for (int j = 0; j < TN; j++) {
            long long n = n0 + tx*TN + j;
            float v = acc[i][j];
            if (addC) v += addC[m*ldc + n];
            C[m*ldc + n] = v;
        }
    }
}

// ---------------- embedding gather -----------------------------------------
__global__ void embed_kernel(const int* __restrict__ idx,
                             const float* __restrict__ wte,
                             float* __restrict__ x)
{
    int t = blockIdx.x;
    const float* src = wte + (long long)idx[t] * N_EMBD;
    float* dst = x + (long long)t * N_EMBD;
    for (int e = threadIdx.x; e < N_EMBD; e += blockDim.x) dst[e] = src[e];
}

// ---------------- rmsnorm ---------------------------------------------------
__global__ void rmsnorm_kernel(const float* __restrict__ x,
                               const float* __restrict__ w,
                               float* __restrict__ out)
{
    int t = blockIdx.x;
    const float* row = x + (long long)t * N_EMBD;
    float s = 0.f;
    for (int e = threadIdx.x; e < N_EMBD; e += blockDim.x) {
        float v = row[e]; s += v * v;
    }
    __shared__ float red[32];
    #pragma unroll
    for (int o = 16; o; o >>= 1) s += __shfl_xor_sync(0xffffffffu, s, o);
    if ((threadIdx.x & 31) == 0) red[threadIdx.x >> 5] = s;
    __syncthreads();
    if (threadIdx.x < 32) {
        float v = (threadIdx.x < (blockDim.x >> 5)) ? red[threadIdx.x] : 0.f;
        #pragma unroll
        for (int o = 16; o; o >>= 1) v += __shfl_xor_sync(0xffffffffu, v, o);
        if (threadIdx.x == 0) red[0] = v;
    }
    __syncthreads();
    float r = rsqrtf(red[0] * (1.f / N_EMBD) + 1e-5f);
    float* dst = out + (long long)t * N_EMBD;
    for (int e = threadIdx.x; e < N_EMBD; e += blockDim.x)
        dst[e] = row[e] * r * w[e];
}

// ---------------- qkv postprocess: rope + elu+1 + scatter -------------------
__global__ void qkv_post_kernel(const float* __restrict__ qkv,
                                float* __restrict__ q,
                                float* __restrict__ k,
                                float* __restrict__ vT)
{
    int t = blockIdx.x;
    const float LN_BASE = 9.210340371976184f;  // ln(10000)
    // i over (group, slot(6), j(64)) = 1536 pairs
    for (int i = threadIdx.x; i < N_GROUPS * 6 * 64; i += blockDim.x) {
        int j    = i & 63;
        int slot = (i >> 6) % 6;
        int g    = i / (6 * 64);
        const float* src = qkv + (long long)t * QKV_DIM + (g * 6 + slot) * HEAD_SIZE;
        float x1 = src[j];
        float x2 = src[j + 64];
        if (slot < 5) {
            float theta = expf(-(2.f * j / 128.f) * LN_BASE);
            float ang = (float)t * theta;
            float sv, cv;
            sincosf(ang, &sv, &cv);
            float o1 = x1 * cv - x2 * sv;
            float o2 = x1 * sv + x2 * cv;
            // elu(z)+1 : z>0 ? z+1 : exp(z)
            o1 = (o1 > 0.f) ? (o1 + 1.f) : expf(o1);
            o2 = (o2 > 0.f) ? (o2 + 1.f) : expf(o2);
            if (slot < 4) {
                int h = g * 4 + slot;
                float* dst = q + ((long long)h * T_SEQ + t) * HEAD_SIZE;
                dst[j] = o1; dst[j + 64] = o2;
            } else {
                float* dst = k + ((long long)g * T_SEQ + t) * HEAD_SIZE;
                dst[j] = o1; dst[j + 64] = o2;
            }
        } else {
            vT[((long long)g * HEAD_SIZE + j) * T_SEQ + t]      = x1;
            vT[((long long)g * HEAD_SIZE + j + 64) * T_SEQ + t] = x2;
        }
    }
}

// ---------------- masked scale + row-sum normalize (linear attention) -------
__global__ void __launch_bounds__(256)
attn_norm_kernel(float* __restrict__ S)
{
    int t = blockIdx.x;
    int h = blockIdx.y;
    float* row = S + ((long long)h * T_SEQ + t) * T_SEQ;
    const float scale = 0.08838834764831845f;  // 1/sqrt(128)
    float v[8];
    float sum = 0.f;
    #pragma unroll
    for (int i = 0; i < 8; i++) {
        int s = i * 256 + threadIdx.x;
        float x = row[s];
        x = (s <= t) ? x * scale : 0.f;
        v[i] = x;
        sum += x;
    }
    __shared__ float red[32];
    #pragma unroll
    for (int o = 16; o; o >>= 1) sum += __shfl_xor_sync(0xffffffffu, sum, o);
    if ((threadIdx.x & 31) == 0) red[threadIdx.x >> 5] = sum;
    __syncthreads();
    if (threadIdx.x < 32) {
        float x = (threadIdx.x < 8) ? red[threadIdx.x] : 0.f;
        #pragma unroll
        for (int o = 4; o; o >>= 1) x += __shfl_xor_sync(0xffffffffu, x, o);
        if (threadIdx.x == 0) red[0] = x;
    }
    __syncthreads();
    float inv = 1.f / (red[0] + 1e-8f);
    #pragma unroll
    for (int i = 0; i < 8; i++)
        row[i * 256 + threadIdx.x] = v[i] * inv;
}

// ---------------- swiglu: a = silu(a) * b -----------------------------------
__global__ void swiglu_kernel(float* __restrict__ a, const float* __restrict__ b)
{
    long long i = (long long)blockIdx.x * blockDim.x + threadIdx.x;
    if (i < (long long)T_SEQ * INTER) {
        float x = a[i];
        float sig = 1.f / (1.f + expf(-x));
        a[i] = x * sig * b[i];
    }
}

// ---------------- orchestration ---------------------------------------------
extern "C" void kernel_launch(void* const* d_in, const int* in_sizes, int n_in,
                              void* d_out, int out_size)
{
    const int*   idx       = (const int*)  d_in[0];
    const float* wte       = (const float*)d_in[1];
    const float* attn_w    = (const float*)d_in[2];
    const float* proj_w    = (const float*)d_in[3];
    const float* w1        = (const float*)d_in[4];
    const float* w2        = (const float*)d_in[5];
    const float* w3        = (const float*)d_in[6];
    const float* norm1_w   = (const float*)d_in[7];
    const float* norm2_w   = (const float*)d_in[8];
    const float* ln_f_w    = (const float*)d_in[9];
    const float* lm_head_w = (const float*)d_in[10];
    float* out = (float*)d_out;

    float *x, *n, *qkv, *q, *k, *vT, *S, *y, *h1, *h2;
    cudaGetSymbolAddress((void**)&x,   g_x);
    cudaGetSymbolAddress((void**)&n,   g_n);
    cudaGetSymbolAddress((void**)&qkv, g_qkv);
    cudaGetSymbolAddress((void**)&q,   g_q);
    cudaGetSymbolAddress((void**)&k,   g_k);
    cudaGetSymbolAddress((void**)&vT,  g_vT);
    cudaGetSymbolAddress((void**)&S,   g_S);
    cudaGetSymbolAddress((void**)&y,   g_y);
    cudaGetSymbolAddress((void**)&h1,  g_h1);
    cudaGetSymbolAddress((void**)&h2,  g_h2);

    const long long TT = (long long)T_SEQ * T_SEQ;
    const long long TH = (long long)T_SEQ * HEAD_SIZE;

    embed_kernel<<<T_SEQ, 256>>>(idx, wte, x);

    for (int l = 0; l < 2; l++) {
        const float* aw = attn_w + (long long)l * QKV_DIM * N_EMBD;
        const float* pw = proj_w + (long long)l * N_EMBD * N_EMBD;
        const float* w1l = w1 + (long long)l * INTER * N_EMBD;
        const float* w2l = w2 + (long long)l * INTER * N_EMBD;
        const float* w3l = w3 + (long long)l * N_EMBD * INTER;

        // n1 = rmsnorm(x)
        rmsnorm_kernel<<<T_SEQ, 256>>>(x, norm1_w + l * N_EMBD, n);

        // qkv = n1 @ attn_w^T   (2048 x 3072, K=2048)
        gemm_nt<<<dim3(QKV_DIM/BN, T_SEQ/BM, 1), 256>>>(
            n, N_EMBD, 0, aw, N_EMBD, 0, 1,
            qkv, QKV_DIM, 0, nullptr, 0, N_EMBD);

        // rope + elu+1 + scatter q/k/vT
        qkv_post_kernel<<<T_SEQ, 512>>>(qkv, q, k, vT);

        // S[h] = q[h] @ k[h/4]^T   (2048 x 2048, K=128), batched over 16 heads
        gemm_nt<<<dim3(T_SEQ/BN, T_SEQ/BM, N_HEADS), 256>>>(
            q, HEAD_SIZE, TH, k, HEAD_SIZE, TH, 4,
            S, T_SEQ, TT, nullptr, 0, HEAD_SIZE);

        // mask * scale, normalize by row sum
        attn_norm_kernel<<<dim3(T_SEQ, N_HEADS), 256>>>(S);

        // y[:, h*128:(h+1)*128] = P[h] @ vT[h/4]^T   (2048 x 128, K=2048)
        gemm_nt<<<dim3(HEAD_SIZE/BN, T_SEQ/BM, N_HEADS), 256>>>(
            S, T_SEQ, TT, vT, T_SEQ, (long long)HEAD_SIZE * T_SEQ, 4,
            y, N_EMBD, HEAD_SIZE, nullptr, 0, T_SEQ);

        // x = x + y @ proj_w^T
        gemm_nt<<<dim3(N_EMBD/BN, T_SEQ/BM, 1), 256>>>(
            y, N_EMBD, 0, pw, N_EMBD, 0, 1,
            x, N_EMBD, 0, x, 0, N_EMBD);

        // n2 = rmsnorm(x)
        rmsnorm_kernel<<<T_SEQ, 256>>>(x, norm2_w + l * N_EMBD, n);

        // h1 = n2 @ w1^T ; h2 = n2 @ w2^T  (2048 x 5632, K=2048)
        gemm_nt<<<dim3(INTER/BN, T_SEQ/BM, 1), 256>>>(
            n, N_EMBD, 0, w1l, N_EMBD, 0, 1,
            h1, INTER, 0, nullptr, 0, N_EMBD);
        gemm_nt<<<dim3(INTER/BN, T_SEQ/BM, 1), 256>>>(
            n, N_EMBD, 0, w2l, N_EMBD, 0, 1,
            h2, INTER, 0, nullptr, 0, N_EMBD);

        // h1 = silu(h1) * h2
        swiglu_kernel<<<(T_SEQ * INTER) / 256, 256>>>(h1, h2);

        // x = x + h1 @ w3^T  (2048 x 2048, K=5632)
        gemm_nt<<<dim3(N_EMBD/BN, T_SEQ/BM, 1), 256>>>(
            h1, INTER, 0, w3l, INTER, 0, 1,
            x, N_EMBD, 0, x, 0, INTER);
    }

    // final norm + lm_head
    rmsnorm_kernel<<<T_SEQ, 256>>>(x, ln_f_w, n);
    gemm_nt<<<dim3(VOCAB/BN, T_SEQ/BM, 1), 256>>>(
        n, N_EMBD, 0, lm_head_w, N_EMBD, 0, 1,
        out, VOCAB, 0, nullptr, 0, N_EMBD);
}

// round 3
// speedup vs baseline: 1.5006x; 1.5006x over previous
#include <cuda_runtime.h>
#include <math.h>
#include <stdint.h>

#define T_SEQ 2048
#define N_EMBD 2048
#define N_HEADS 16
#define N_GROUPS 4
#define HEAD_SIZE 128
#define INTER 5632
#define VOCAB 32000
#define QKV_DIM 3072

// ---------------- scratch -------------------------------------------------
__device__ float g_x  [T_SEQ * N_EMBD];
__device__ float g_nh [T_SEQ * N_EMBD];
__device__ float g_nl [T_SEQ * N_EMBD];
__device__ float g_qkv[T_SEQ * QKV_DIM];
__device__ float g_qh [N_HEADS  * T_SEQ * HEAD_SIZE];
__device__ float g_ql [N_HEADS  * T_SEQ * HEAD_SIZE];
__device__ float g_kh [N_GROUPS * T_SEQ * HEAD_SIZE];
__device__ float g_kl [N_GROUPS * T_SEQ * HEAD_SIZE];
__device__ float g_vh [N_GROUPS * HEAD_SIZE * T_SEQ];
__device__ float g_vl [N_GROUPS * HEAD_SIZE * T_SEQ];
__device__ float g_S  [N_HEADS * T_SEQ * T_SEQ];
__device__ float g_Sl [N_HEADS * T_SEQ * T_SEQ];
__device__ float g_yh [T_SEQ * N_EMBD];
__device__ float g_yl [T_SEQ * N_EMBD];
__device__ float g_h1 [T_SEQ * INTER];
__device__ float g_h2 [T_SEQ * INTER];
__device__ float g_h1h[T_SEQ * INTER];
__device__ float g_h1l[T_SEQ * INTER];
__device__ float g_awh[2 * QKV_DIM * N_EMBD];
__device__ float g_awl[2 * QKV_DIM * N_EMBD];
__device__ float g_pwh[2 * N_EMBD * N_EMBD];
__device__ float g_pwl[2 * N_EMBD * N_EMBD];
__device__ float g_w1h[2 * INTER * N_EMBD];
__device__ float g_w1l[2 * INTER * N_EMBD];
__device__ float g_w2h[2 * INTER * N_EMBD];
__device__ float g_w2l[2 * INTER * N_EMBD];
__device__ float g_w3h[2 * N_EMBD * INTER];
__device__ float g_w3l[2 * N_EMBD * INTER];
__device__ float g_lmh[VOCAB * N_EMBD];
__device__ float g_lml[VOCAB * N_EMBD];

// ---------------- helpers ---------------------------------------------------
__device__ __forceinline__ uint32_t cvta_smem(const void* p) {
    uint32_t a;
    asm("{.reg .u64 t; cvta.to.shared.u64 t, %1; cvt.u32.u64 %0, t;}" : "=r"(a) : "l"(p));
    return a;
}

__device__ __forceinline__ float tf32_rna(float x) {
    uint32_t u;
    asm("cvt.rna.tf32.f32 %0, %1;" : "=r"(u) : "f"(x));
    return __uint_as_float(u);
}

#define CP16(dst, src) asm volatile("cp.async.cg.shared.global [%0], [%1], 16;" :: "r"(dst), "l"(src))
#define CP_COMMIT() asm volatile("cp.async.commit_group;" ::: "memory")

__device__ __forceinline__ void mma8(float* d, const uint32_t* a, const uint32_t* b) {
    asm volatile(
        "mma.sync.aligned.m16n8k8.row.col.f32.tf32.tf32.f32 "
        "{%0,%1,%2,%3}, {%4,%5,%6,%7}, {%8,%9}, {%0,%1,%2,%3};"
        : "+f"(d[0]), "+f"(d[1]), "+f"(d[2]), "+f"(d[3])
        : "r"(a[0]), "r"(a[1]), "r"(a[2]), "r"(a[3]), "r"(b[0]), "r"(b[1]));
}

// ---------------- mma.sync tf32x3 NT GEMM -----------------------------------
// C[m,n] = sum_k A[m,k]*B[n,k],  A=Ahi+Alo, B=Bhi+Blo
// mode: 0 plain, 1 causal tile skip (S), 2 causal K-clamp (PV)
#define BMT 128
#define BNT 128
#define KB  32
#define LDT 36                              // padded smem row stride (floats)
#define SUBF (128 * LDT)                    // floats per sub-tile
#define STGF (4 * SUBF)                     // floats per stage

__global__ void __launch_bounds__(256)
gemm_mma(const float* __restrict__ Ahi, const float* __restrict__ Alo, int lda, long long sA,
         const float* __restrict__ Bhi, const float* __restrict__ Blo, int ldb, long long sB, int bdiv,
         float* C, float* Chi, float* Clo, int ldc, long long sC,
         const float* __restrict__ addC,
         int K, int mode)
{
    extern __shared__ __align__(16) float smem[];
    const int m0 = blockIdx.y * BMT;
    const int n0 = blockIdx.x * BNT;
    if (mode == 1 && n0 > m0 + BMT - 1) return;
    const int Keff = (mode == 2) ? min(K, m0 + BMT) : K;
    const int KT = Keff / KB;
    const int z = blockIdx.z;
    Ahi += (long long)z * sA;  Alo += (long long)z * sA;
    Bhi += (long long)(z / bdiv) * sB;  Blo += (long long)(z / bdiv) * sB;
    const long long coff = (long long)z * sC;

    const int tid  = threadIdx.x;
    const int lane = tid & 31;
    const int wid  = tid >> 5;
    const int wm   = (wid & 1) * 64;     // warp m offset
    const int wn   = (wid >> 1) * 32;    // warp n offset
    const uint32_t sbase = cvta_smem(smem);

    // ---- async tile loader ----
    auto load_tile = [&](int kt) {
        const int s = kt & 1;
        const uint32_t stb = sbase + (uint32_t)(s * STGF) * 4u;
        const float* srcs[4] = { Ahi, Alo, Bhi, Blo };
        const int    lds [4] = { lda, lda, ldb, ldb };
        const int    rows[4] = { m0, m0, n0, n0 };
        #pragma unroll
        for (int sub = 0; sub < 4; sub++) {
            const float* P = srcs[sub];
            const int ld = lds[sub];
            const int r0 = rows[sub];
            const uint32_t db = stb + (uint32_t)(sub * SUBF) * 4u;
            #pragma unroll
            for (int it = 0; it < 4; it++) {
                int i = it * 256 + tid;          // 1024 chunks of 16B
                int r = i >> 3, c = i & 7;
                uint32_t dst = db + (uint32_t)(r * LDT + c * 4) * 4u;
                const char* sp = (const char*)(P + (long long)(r0 + r) * ld + kt * KB) + c * 16;
                CP16(dst, sp);
            }
        }
        CP_COMMIT();
    };

    float acc[4][4][4];
    #pragma unroll
    for (int a = 0; a < 4; a++)
        #pragma unroll
        for (int b = 0; b < 4; b++)
            #pragma unroll
            for (int c = 0; c < 4; c++) acc[a][b][c] = 0.f;

    load_tile(0);
    if (KT > 1) load_tile(1);

    for (int kt = 0; kt < KT; kt++) {
        if (kt + 1 < KT) asm volatile("cp.async.wait_group 1;" ::: "memory");
        else             asm volatile("cp.async.wait_group 0;" ::: "memory");
        __syncthreads();

        const float* st = smem + (kt & 1) * STGF;
        const float* sAh = st;
        const float* sAl = st + SUBF;
        const float* sBh = st + 2 * SUBF;
        const float* sBl = st + 3 * SUBF;

        #pragma unroll
        for (int ks = 0; ks < 4; ks++) {
            const int kc = ks * 8 + (lane & 3);
            uint32_t Ah[4][4], Al[4][4], Bh[4][2], Bl[4][2];
            #pragma unroll
            for (int mc = 0; mc < 4; mc++) {
                int r = wm + mc * 16 + (lane >> 2);
                int i0 = r * LDT + kc;
                int i1 = (r + 8) * LDT + kc;
                Ah[mc][0] = __float_as_uint(sAh[i0]);
                Ah[mc][1] = __float_as_uint(sAh[i1]);
                Ah[mc][2] = __float_as_uint(sAh[i0 + 4]);
                Ah[mc][3] = __float_as_uint(sAh[i1 + 4]);
                Al[mc][0] = __float_as_uint(sAl[i0]);
                Al[mc][1] = __float_as_uint(sAl[i1]);
                Al[mc][2] = __float_as_uint(sAl[i0 + 4]);
                Al[mc][3] = __float_as_uint(sAl[i1 + 4]);
            }
            #pragma unroll
            for (int nc = 0; nc < 4; nc++) {
                int n = wn + nc * 8 + (lane >> 2);
                int i0 = n * LDT + kc;
                Bh[nc][0] = __float_as_uint(sBh[i0]);
                Bh[nc][1] = __float_as_uint(sBh[i0 + 4]);
                Bl[nc][0] = __float_as_uint(sBl[i0]);
                Bl[nc][1] = __float_as_uint(sBl[i0 + 4]);
            }
            #pragma unroll
            for (int mc = 0; mc < 4; mc++)
                #pragma unroll
                for (int nc = 0; nc < 4; nc++) {
                    mma8(acc[mc][nc], Ah[mc], Bh[nc]);
                    mma8(acc[mc][nc], Ah[mc], Bl[nc]);
                    mma8(acc[mc][nc], Al[mc], Bh[nc]);
                }
        }
        __syncthreads();
        if (kt + 2 < KT) load_tile(kt + 2);
    }

    // ---- epilogue: registers -> gmem (2-float vectors, coalesced) ----
    #pragma unroll
    for (int mc = 0; mc < 4; mc++)
        #pragma unroll
        for (int nc = 0; nc < 4; nc++) {
            int c0 = n0 + wn + nc * 8 + (lane & 3) * 2;
            #pragma unroll
            for (int rr = 0; rr < 2; rr++) {
                int row = m0 + wm + mc * 16 + (lane >> 2) + rr * 8;
                float v0 = acc[mc][nc][rr * 2];
                float v1 = acc[mc][nc][rr * 2 + 1];
                long long off = coff + (long long)row * ldc + c0;
                if (addC) { v0 += addC[off]; v1 += addC[off + 1]; }
                if (C) { C[off] = v0; C[off + 1] = v1; }
                if (Chi) {
                    float h0 = tf32_rna(v0), h1 = tf32_rna(v1);
                    Chi[off] = h0;            Chi[off + 1] = h1;
                    Clo[off] = tf32_rna(v0 - h0);
                    Clo[off + 1] = tf32_rna(v1 - h1);
                }
            }
        }
}

// ---------------- elementwise kernels --------------------------------------
__global__ void split_kernel(const float* __restrict__ w,
                             float* __restrict__ hi, float* __restrict__ lo, int n)
{
    int i = blockIdx.x * blockDim.x + threadIdx.x;
    if (i < n) {
        float x = w[i];
        float h = tf32_rna(x);
        hi[i] = h;
        lo[i] = tf32_rna(x - h);
    }
}

__global__ void embed_kernel(const int* __restrict__ idx,
                             const float* __restrict__ wte, float* __restrict__ x)
{
    int t = blockIdx.x;
    const float* src = wte + (long long)idx[t] * N_EMBD;
    float* dst = x + (long long)t * N_EMBD;
    for (int e = threadIdx.x; e < N_EMBD; e += blockDim.x) dst[e] = src[e];
}

__global__ void rmsnorm_kernel(const float* __restrict__ x, const float* __restrict__ w,
                               float* __restrict__ ohi, float* __restrict__ olo)
{
    int t = blockIdx.x;
    const float* row = x + (long long)t * N_EMBD;
    float s = 0.f;
    for (int e = threadIdx.x; e < N_EMBD; e += blockDim.x) { float v = row[e]; s += v * v; }
    __shared__ float red[32];
    #pragma unroll
    for (int o = 16; o; o >>= 1) s += __shfl_xor_sync(0xffffffffu, s, o);
    if ((threadIdx.x & 31) == 0) red[threadIdx.x >> 5] = s;
    __syncthreads();
    if (threadIdx.x < 32) {
        float v = (threadIdx.x < (blockDim.x >> 5)) ? red[threadIdx.x] : 0.f;
        #pragma unroll
        for (int o = 16; o; o >>= 1) v += __shfl_xor_sync(0xffffffffu, v, o);
        if (threadIdx.x == 0) red[0] = v;
    }
    __syncthreads();
    float r = rsqrtf(red[0] * (1.f / N_EMBD) + 1e-5f);
    for (int e = threadIdx.x; e < N_EMBD; e += blockDim.x) {
        float v = row[e] * r * w[e];
        float h = tf32_rna(v);
        ohi[(long long)t * N_EMBD + e] = h;
        olo[(long long)t * N_EMBD + e] = tf32_rna(v - h);
    }
}

__global__ void qkv_post_kernel(const float* __restrict__ qkv,
                                float* __restrict__ qh, float* __restrict__ ql,
                                float* __restrict__ kh, float* __restrict__ kl,
                                float* __restrict__ vh, float* __restrict__ vl)
{
    int t = blockIdx.x;
    const float LN_BASE = 9.210340371976184f;
    for (int i = threadIdx.x; i < N_GROUPS * 6 * 64; i += blockDim.x) {
        int j    = i & 63;
        int slot = (i >> 6) % 6;
        int g    = i / (6 * 64);
        const float* src = qkv + (long long)t * QKV_DIM + (g * 6 + slot) * HEAD_SIZE;
        float x1 = src[j];
        float x2 = src[j + 64];
        if (slot < 5) {
            float theta = expf(-(2.f * j / 128.f) * LN_BASE);
            float ang = (float)t * theta;
            float sv, cv;
            sincosf(ang, &sv, &cv);
            float o1 = x1 * cv - x2 * sv;
            float o2 = x1 * sv + x2 * cv;
            o1 = (o1 > 0.f) ? (o1 + 1.f) : expf(o1);
            o2 = (o2 > 0.f) ? (o2 + 1.f) : expf(o2);
            float h1v = tf32_rna(o1), l1v = tf32_rna(o1 - h1v);
            float h2v = tf32_rna(o2), l2v = tf32_rna(o2 - h2v);
            if (slot < 4) {
                int h = g * 4 + slot;
                long long b = ((long long)h * T_SEQ + t) * HEAD_SIZE;
                qh[b + j] = h1v; qh[b + j + 64] = h2v;
                ql[b + j] = l1v; ql[b + j + 64] = l2v;
            } else {
                long long b = ((long long)g * T_SEQ + t) * HEAD_SIZE;
                kh[b + j] = h1v; kh[b + j + 64] = h2v;
                kl[b + j] = l1v; kl[b + j + 64] = l2v;
            }
        } else {
            float ha = tf32_rna(x1), la = tf32_rna(x1 - ha);
            float hb = tf32_rna(x2), lb = tf32_rna(x2 - hb);
            long long b0 = ((long long)g * HEAD_SIZE + j) * T_SEQ + t;
            long long b1 = ((long long)g * HEAD_SIZE + j + 64) * T_SEQ + t;
            vh[b0] = ha; vl[b0] = la;
            vh[b1] = hb; vl[b1] = lb;
        }
    }
}

__global__ void __launch_bounds__(256)
attn_norm_kernel(float* __restrict__ S, float* __restrict__ Sl)
{
    int t = blockIdx.x;
    int h = blockIdx.y;
    long long base = ((long long)h * T_SEQ + t) * T_SEQ;
    float* row = S + base;
    float* rowl = Sl + base;
    const float scale = 0.08838834764831845f;
    float v[8];
    float sum = 0.f;
    #pragma unroll
    for (int i = 0; i < 8; i++) {
        int s = i * 256 + threadIdx.x;
        float x = row[s];
        x = (s <= t) ? x * scale : 0.f;
        v[i] = x;
        sum += x;
    }
    __shared__ float red[32];
    #pragma unroll
    for (int o = 16; o; o >>= 1) sum += __shfl_xor_sync(0xffffffffu, sum, o);
    if ((threadIdx.x & 31) == 0) red[threadIdx.x >> 5] = sum;
    __syncthreads();
    if (threadIdx.x < 32) {
        float x = (threadIdx.x < 8) ? red[threadIdx.x] : 0.f;
        #pragma unroll
        for (int o = 4; o; o >>= 1) x += __shfl_xor_sync(0xffffffffu, x, o);
        if (threadIdx.x == 0) red[0] = x;
    }
    __syncthreads();
    float inv = 1.f / (red[0] + 1e-8f);
    #pragma unroll
    for (int i = 0; i < 8; i++) {
        float p = v[i] * inv;
        float hh = tf32_rna(p);
        row[i * 256 + threadIdx.x]  = hh;
        rowl[i * 256 + threadIdx.x] = tf32_rna(p - hh);
    }
}

__global__ void swiglu_kernel(const float* __restrict__ a, const float* __restrict__ b,
                              float* __restrict__ ohi, float* __restrict__ olo)
{
    long long i = (long long)blockIdx.x * blockDim.x + threadIdx.x;
    if (i < (long long)T_SEQ * INTER) {
        float x = a[i];
        float sig = 1.f / (1.f + expf(-x));
        float v = x * sig * b[i];
        float h = tf32_rna(v);
        ohi[i] = h;
        olo[i] = tf32_rna(v - h);
    }
}

// ---------------- orchestration ---------------------------------------------
extern "C" void kernel_launch(void* const* d_in, const int* in_sizes, int n_in,
                              void* d_out, int out_size)
{
    const int*   idx       = (const int*)  d_in[0];
    const float* wte       = (const float*)d_in[1];
    const float* attn_w    = (const float*)d_in[2];
    const float* proj_w    = (const float*)d_in[3];
    const float* w1        = (const float*)d_in[4];
    const float* w2        = (const float*)d_in[5];
    const float* w3        = (const float*)d_in[6];
    const float* norm1_w   = (const float*)d_in[7];
    const float* norm2_w   = (const float*)d_in[8];
    const float* ln_f_w    = (const float*)d_in[9];
    const float* lm_head_w = (const float*)d_in[10];
    float* out = (float*)d_out;

    float *x, *nh, *nl, *qkv, *qh, *ql, *kh, *kl, *vh, *vl, *S, *Sl, *yh, *yl,
          *h1, *h2, *h1h, *h1l, *awh, *awl, *pwh, *pwl, *w1h, *w1l, *w2h, *w2l,
          *w3h, *w3l, *lmh, *lml;
    cudaGetSymbolAddress((void**)&x,   g_x);
    cudaGetSymbolAddress((void**)&nh,  g_nh);
    cudaGetSymbolAddress((void**)&nl,  g_nl);
    cudaGetSymbolAddress((void**)&qkv, g_qkv);
    cudaGetSymbolAddress((void**)&qh,  g_qh);
    cudaGetSymbolAddress((void**)&ql,  g_ql);
    cudaGetSymbolAddress((void**)&kh,  g_kh);
    cudaGetSymbolAddress((void**)&kl,  g_kl);
    cudaGetSymbolAddress((void**)&vh,  g_vh);
    cudaGetSymbolAddress((void**)&vl,  g_vl);
    cudaGetSymbolAddress((void**)&S,   g_S);
    cudaGetSymbolAddress((void**)&Sl,  g_Sl);
    cudaGetSymbolAddress((void**)&yh,  g_yh);
    cudaGetSymbolAddress((void**)&yl,  g_yl);
    cudaGetSymbolAddress((void**)&h1,  g_h1);
    cudaGetSymbolAddress((void**)&h2,  g_h2);
    cudaGetSymbolAddress((void**)&h1h, g_h1h);
    cudaGetSymbolAddress((void**)&h1l, g_h1l);
    cudaGetSymbolAddress((void**)&awh, g_awh);
    cudaGetSymbolAddress((void**)&awl, g_awl);
    cudaGetSymbolAddress((void**)&pwh, g_pwh);
    cudaGetSymbolAddress((void**)&pwl, g_pwl);
    cudaGetSymbolAddress((void**)&w1h, g_w1h);
    cudaGetSymbolAddress((void**)&w1l, g_w1l);
    cudaGetSymbolAddress((void**)&w2h, g_w2h);
    cudaGetSymbolAddress((void**)&w2l, g_w2l);
    cudaGetSymbolAddress((void**)&w3h, g_w3h);
    cudaGetSymbolAddress((void**)&w3l, g_w3l);
    cudaGetSymbolAddress((void**)&lmh, g_lmh);
    cudaGetSymbolAddress((void**)&lml, g_lml);

    const int SMEM = 2 * STGF * 4;  // 2 stages * 18432 floats = 147456 B
    cudaFuncSetAttribute(gemm_mma, cudaFuncAttributeMaxDynamicSharedMemorySize, SMEM);

    const long long TT = (long long)T_SEQ * T_SEQ;
    const long long TH = (long long)T_SEQ * HEAD_SIZE;

    {
        int n;
        n = 2 * QKV_DIM * N_EMBD; split_kernel<<<(n + 255) / 256, 256>>>(attn_w, awh, awl, n);
        n = 2 * N_EMBD * N_EMBD;  split_kernel<<<(n + 255) / 256, 256>>>(proj_w, pwh, pwl, n);
        n = 2 * INTER * N_EMBD;   split_kernel<<<(n + 255) / 256, 256>>>(w1, w1h, w1l, n);
        n = 2 * INTER * N_EMBD;   split_kernel<<<(n + 255) / 256, 256>>>(w2, w2h, w2l, n);
        n = 2 * N_EMBD * INTER;   split_kernel<<<(n + 255) / 256, 256>>>(w3, w3h, w3l, n);
        n = VOCAB * N_EMBD;       split_kernel<<<(n + 255) / 256, 256>>>(lm_head_w, lmh, lml, n);
    }

    embed_kernel<<<T_SEQ, 256>>>(idx, wte, x);

    for (int l = 0; l < 2; l++) {
        const long long awo = (long long)l * QKV_DIM * N_EMBD;
        const long long pwo = (long long)l * N_EMBD * N_EMBD;
        const long long w12o = (long long)l * INTER * N_EMBD;
        const long long w3o = (long long)l * N_EMBD * INTER;

        rmsnorm_kernel<<<T_SEQ, 256>>>(x, norm1_w + l * N_EMBD, nh, nl);

        // qkv = n1 @ attn_w^T
        gemm_mma<<<dim3(QKV_DIM / BNT, T_SEQ / BMT, 1), 256, SMEM>>>(
            nh, nl, N_EMBD, 0, awh + awo, awl + awo, N_EMBD, 0, 1,
            qkv, nullptr, nullptr, QKV_DIM, 0, nullptr, N_EMBD, 0);

        qkv_post_kernel<<<T_SEQ, 512>>>(qkv, qh, ql, kh, kl, vh, vl);

        // S[h] = q[h] @ k[g]^T  (causal tile skip)
        gemm_mma<<<dim3(T_SEQ / BNT, T_SEQ / BMT, N_HEADS), 256, SMEM>>>(
            qh, ql, HEAD_SIZE, TH, kh, kl, HEAD_SIZE, TH, 4,
            S, nullptr, nullptr, T_SEQ, TT, nullptr, HEAD_SIZE, 1);

        attn_norm_kernel<<<dim3(T_SEQ, N_HEADS), 256>>>(S, Sl);

        // y[:, h] = P[h] @ vT[g]^T  (K clamped at diagonal)
        gemm_mma<<<dim3(HEAD_SIZE / BNT, T_SEQ / BMT, N_HEADS), 256, SMEM>>>(
            S, Sl, T_SEQ, TT, vh, vl, T_SEQ, (long long)HEAD_SIZE * T_SEQ, 4,
            nullptr, yh, yl, N_EMBD, HEAD_SIZE, nullptr, T_SEQ, 2);

        // x = x + y @ proj_w^T
        gemm_mma<<<dim3(N_EMBD / BNT, T_SEQ / BMT, 1), 256, SMEM>>>(
            yh, yl, N_EMBD, 0, pwh + pwo, pwl + pwo, N_EMBD, 0, 1,
            x, nullptr, nullptr, N_EMBD, 0, x, N_EMBD, 0);

        rmsnorm_kernel<<<T_SEQ, 256>>>(x, norm2_w + l * N_EMBD, nh, nl);

        gemm_mma<<<dim3(INTER / BNT, T_SEQ / BMT, 1), 256, SMEM>>>(
            nh, nl, N_EMBD, 0, w1h + w12o, w1l + w12o, N_EMBD, 0, 1,
            h1, nullptr, nullptr, INTER, 0, nullptr, N_EMBD, 0);
        gemm_mma<<<dim3(INTER / BNT, T_SEQ / BMT, 1), 256, SMEM>>>(
            nh, nl, N_EMBD, 0, w2h + w12o, w2l + w12o, N_EMBD, 0, 1,
            h2, nullptr, nullptr, INTER, 0, nullptr, N_EMBD, 0);

        swiglu_kernel<<<(T_SEQ * INTER) / 256, 256>>>(h1, h2, h1h, h1l);

        // x = x + h @ w3^T
        gemm_mma<<<dim3(N_EMBD / BNT, T_SEQ / BMT, 1), 256, SMEM>>>(
            h1h, h1l, INTER, 0, w3h + w3o, w3l + w3o, INTER, 0, 1,
            x, nullptr, nullptr, N_EMBD, 0, x, INTER, 0);
    }

    rmsnorm_kernel<<<T_SEQ, 256>>>(x, ln_f_w, nh, nl);
    gemm_mma<<<dim3(VOCAB / BNT, T_SEQ / BMT, 1), 256, SMEM>>>(
        nh, nl, N_EMBD, 0, lmh, lml, N_EMBD, 0, 1,
        out, nullptr, nullptr, VOCAB, 0, nullptr, N_EMBD, 0);
}

// round 4
// speedup vs baseline: 2.6575x; 1.7709x over previous
#include <cuda_runtime.h>
#include <cuda_fp16.h>
#include <math.h>
#include <stdint.h>

#define T_SEQ 2048
#define N_EMBD 2048
#define N_HEADS 16
#define N_GROUPS 4
#define HEAD_SIZE 128
#define INTER 5632
#define VOCAB 32000
#define QKV_DIM 3072

// ---------------- scratch ---------------------------------------------------
__device__ float g_x  [T_SEQ * N_EMBD];
__device__ float g_n  [T_SEQ * N_EMBD];
__device__ float g_qkv[T_SEQ * QKV_DIM];
__device__ float g_q  [N_HEADS  * T_SEQ * HEAD_SIZE];
__device__ float g_k  [N_GROUPS * T_SEQ * HEAD_SIZE];
__device__ float g_vT [N_GROUPS * HEAD_SIZE * T_SEQ];
__device__ float g_S  [N_HEADS * T_SEQ * T_SEQ];
__device__ float g_y  [T_SEQ * N_EMBD];
__device__ float g_h1 [T_SEQ * INTER];
__device__ float g_h2 [T_SEQ * INTER];

// ---------------- helpers ---------------------------------------------------
__device__ __forceinline__ void mma16(float* d, const uint32_t* a, const uint32_t* b) {
    asm volatile(
        "mma.sync.aligned.m16n8k16.row.col.f32.f16.f16.f32 "
        "{%0,%1,%2,%3}, {%4,%5,%6,%7}, {%8,%9}, {%0,%1,%2,%3};"
        : "+f"(d[0]), "+f"(d[1]), "+f"(d[2]), "+f"(d[3])
        : "r"(a[0]), "r"(a[1]), "r"(a[2]), "r"(a[3]), "r"(b[0]), "r"(b[1]));
}

// split float4 -> hi half2x2 + lo half2x2
__device__ __forceinline__ void split4(float4 v, uint2& hi, uint2& lo) {
    __half2 h01 = __floats2half2_rn(v.x, v.y);
    __half2 h23 = __floats2half2_rn(v.z, v.w);
    float2 f01 = __half22float2(h01);
    float2 f23 = __half22float2(h23);
    __half2 l01 = __floats2half2_rn(v.x - f01.x, v.y - f01.y);
    __half2 l23 = __floats2half2_rn(v.z - f23.x, v.w - f23.y);
    hi.x = *(uint32_t*)&h01; hi.y = *(uint32_t*)&h23;
    lo.x = *(uint32_t*)&l01; lo.y = *(uint32_t*)&l23;
}

// ---------------- fp16x3 NT GEMM (mma.sync m16n8k16) ------------------------
// C[m,n] = sum_k A[m,k]*B[n,k]; fp32 in gmem, split to f16 hi/lo in-kernel.
// mode: 0 plain, 1 causal tile skip (S), 2 causal K-clamp (PV)
// grid: x = M-tiles, y = N-tiles (so CTAs sharing a B tile run together)
#define BMT 128
#define BNT 128
#define KB  32
#define ROWW 20                    // half2-words per smem row (40 halves, padded)
#define SUBW (128 * ROWW)          // words per sub-tile
#define STGW (4 * SUBW)            // words per stage (Ahi,Alo,Bhi,Blo)

__global__ void __launch_bounds__(256)
gemm_f16(const float* __restrict__ A, int lda, long long sA,
         const float* __restrict__ B, int ldb, long long sB, int bdiv,
         float* C, int ldc, long long sC,
         const float* __restrict__ addC,
         int K, int mode)
{
    extern __shared__ __align__(16) uint32_t smw[];
    const int m0 = blockIdx.x * BMT;
    const int n0 = blockIdx.y * BNT;
    if (mode == 1 && n0 > m0 + BMT - 1) return;
    const int Keff = (mode == 2) ? min(K, m0 + BMT) : K;
    const int KT = Keff / KB;
    const int z = blockIdx.z;
    A += (long long)z * sA;
    B += (long long)(z / bdiv) * sB;
    const long long coff = (long long)z * sC;

    const int tid  = threadIdx.x;
    const int lane = tid & 31;
    const int wid  = tid >> 5;
    const int wm   = (wid & 1) * 64;
    const int wn   = (wid >> 1) * 32;

    // register staging for one K-tile (A: 4 float4, B: 4 float4 per thread)
    float4 rA[4], rB[4];
    const int lr = tid >> 3;            // base row pattern (0..31 per chunk)
    const int lc = tid & 7;             // float4 column within 32-float row

    auto ldg_tile = [&](int kt) {
        #pragma unroll
        for (int it = 0; it < 4; it++) {
            int r = it * 32 + lr;
            rA[it] = *(const float4*)(A + (long long)(m0 + r) * lda + kt * KB + lc * 4);
            rB[it] = *(const float4*)(B + (long long)(n0 + r) * ldb + kt * KB + lc * 4);
        }
    };
    auto sts_tile = [&](int s) {
        uint32_t* st = smw + s * STGW;
        #pragma unroll
        for (int it = 0; it < 4; it++) {
            int r = it * 32 + lr;
            int w = r * ROWW + lc * 2;
            uint2 hi, lo;
            split4(rA[it], hi, lo);
            *(uint2*)(st + w) = hi;
            *(uint2*)(st + SUBW + w) = lo;
            split4(rB[it], hi, lo);
            *(uint2*)(st + 2 * SUBW + w) = hi;
            *(uint2*)(st + 3 * SUBW + w) = lo;
        }
    };

    float acc[4][4][4];
    #pragma unroll
    for (int a = 0; a < 4; a++)
        #pragma unroll
        for (int b = 0; b < 4; b++)
            #pragma unroll
            for (int c = 0; c < 4; c++) acc[a][b][c] = 0.f;

    ldg_tile(0);
    sts_tile(0);
    if (KT > 1) ldg_tile(1);
    __syncthreads();

    for (int kt = 0; kt < KT; kt++) {
        if (kt + 1 < KT) sts_tile((kt + 1) & 1);
        if (kt + 2 < KT) ldg_tile(kt + 2);

        const uint32_t* st = smw + (kt & 1) * STGW;
        const uint32_t* sAh = st;
        const uint32_t* sAl = st + SUBW;
        const uint32_t* sBh = st + 2 * SUBW;
        const uint32_t* sBl = st + 3 * SUBW;

        #pragma unroll
        for (int ks = 0; ks < 2; ks++) {
            const int kq = ks * 8 + (lane & 3);
            uint32_t Ah[4][4], Al[4][4], Bh[4][2], Bl[4][2];
            #pragma unroll
            for (int mc = 0; mc < 4; mc++) {
                int r = wm + mc * 16 + (lane >> 2);
                int w0 = r * ROWW + kq;
                int w1 = (r + 8) * ROWW + kq;
                Ah[mc][0] = sAh[w0]; Ah[mc][1] = sAh[w1];
                Ah[mc][2] = sAh[w0 + 4]; Ah[mc][3] = sAh[w1 + 4];
                Al[mc][0] = sAl[w0]; Al[mc][1] = sAl[w1];
                Al[mc][2] = sAl[w0 + 4]; Al[mc][3] = sAl[w1 + 4];
            }
            #pragma unroll
            for (int nc = 0; nc < 4; nc++) {
                int n = wn + nc * 8 + (lane >> 2);
                int w0 = n * ROWW + kq;
                Bh[nc][0] = sBh[w0]; Bh[nc][1] = sBh[w0 + 4];
                Bl[nc][0] = sBl[w0]; Bl[nc][1] = sBl[w0 + 4];
            }
            #pragma unroll
            for (int mc = 0; mc < 4; mc++)
                #pragma unroll
                for (int nc = 0; nc < 4; nc++) {
                    mma16(acc[mc][nc], Ah[mc], Bh[nc]);
                    mma16(acc[mc][nc], Ah[mc], Bl[nc]);
                    mma16(acc[mc][nc], Al[mc], Bh[nc]);
                }
        }
        __syncthreads();
    }

    // ---- epilogue: registers -> gmem (float2, coalesced) ----
    #pragma unroll
    for (int mc = 0; mc < 4; mc++)
        #pragma unroll
        for (int nc = 0; nc < 4; nc++) {
            int c0 = n0 + wn + nc * 8 + (lane & 3) * 2;
            #pragma unroll
            for (int rr = 0; rr < 2; rr++) {
                int row = m0 + wm + mc * 16 + (lane >> 2) + rr * 8;
                float v0 = acc[mc][nc][rr * 2];
                float v1 = acc[mc][nc][rr * 2 + 1];
                long long off = coff + (long long)row * ldc + c0;
                if (addC) { v0 += addC[off]; v1 += addC[off + 1]; }
                C[off] = v0;
                C[off + 1] = v1;
            }
        }
}

// ---------------- elementwise kernels ---------------------------------------
__global__ void embed_kernel(const int* __restrict__ idx,
                             const float* __restrict__ wte, float* __restrict__ x)
{
    int t = blockIdx.x;
    const float* src = wte + (long long)idx[t] * N_EMBD;
    float* dst = x + (long long)t * N_EMBD;
    for (int e = threadIdx.x; e < N_EMBD; e += blockDim.x) dst[e] = src[e];
}

__global__ void rmsnorm_kernel(const float* __restrict__ x, const float* __restrict__ w,
                               float* __restrict__ out)
{
    int t = blockIdx.x;
    const float* row = x + (long long)t * N_EMBD;
    float s = 0.f;
    for (int e = threadIdx.x; e < N_EMBD; e += blockDim.x) { float v = row[e]; s += v * v; }
    __shared__ float red[32];
    #pragma unroll
    for (int o = 16; o; o >>= 1) s += __shfl_xor_sync(0xffffffffu, s, o);
    if ((threadIdx.x & 31) == 0) red[threadIdx.x >> 5] = s;
    __syncthreads();
    if (threadIdx.x < 32) {
        float v = (threadIdx.x < (blockDim.x >> 5)) ? red[threadIdx.x] : 0.f;
        #pragma unroll
        for (int o = 16; o; o >>= 1) v += __shfl_xor_sync(0xffffffffu, v, o);
        if (threadIdx.x == 0) red[0] = v;
    }
    __syncthreads();
    float r = rsqrtf(red[0] * (1.f / N_EMBD) + 1e-5f);
    float* dst = out + (long long)t * N_EMBD;
    for (int e = threadIdx.x; e < N_EMBD; e += blockDim.x)
        dst[e] = row[e] * r * w[e];
}

__global__ void qkv_post_kernel(const float* __restrict__ qkv,
                                float* __restrict__ q,
                                float* __restrict__ k,
                                float* __restrict__ vT)
{
    int t = blockIdx.x;
    const float LN_BASE = 9.210340371976184f;
    for (int i = threadIdx.x; i < N_GROUPS * 6 * 64; i += blockDim.x) {
        int j    = i & 63;
        int slot = (i >> 6) % 6;
        int g    = i / (6 * 64);
        const float* src = qkv + (long long)t * QKV_DIM + (g * 6 + slot) * HEAD_SIZE;
        float x1 = src[j];
        float x2 = src[j + 64];
        if (slot < 5) {
            float theta = expf(-(2.f * j / 128.f) * LN_BASE);
            float ang = (float)t * theta;
            float sv, cv;
            sincosf(ang, &sv, &cv);
            float o1 = x1 * cv - x2 * sv;
            float o2 = x1 * sv + x2 * cv;
            o1 = (o1 > 0.f) ? (o1 + 1.f) : expf(o1);
            o2 = (o2 > 0.f) ? (o2 + 1.f) : expf(o2);
            if (slot < 4) {
                int h = g * 4 + slot;
                float* dst = q + ((long long)h * T_SEQ + t) * HEAD_SIZE;
                dst[j] = o1; dst[j + 64] = o2;
            } else {
                float* dst = k + ((long long)g * T_SEQ + t) * HEAD_SIZE;
                dst[j] = o1; dst[j + 64] = o2;
            }
        } else {
            vT[((long long)g * HEAD_SIZE + j) * T_SEQ + t]      = x1;
            vT[((long long)g * HEAD_SIZE + j + 64) * T_SEQ + t] = x2;
        }
    }
}

__global__ void __launch_bounds__(256)
attn_norm_kernel(float* __restrict__ S)
{
    int t = blockIdx.x;
    int h = blockIdx.y;
    float* row = S + ((long long)h * T_SEQ + t) * T_SEQ;
    const float scale = 0.08838834764831845f;
    float v[8];
    float sum = 0.f;
    #pragma unroll
    for (int i = 0; i < 8; i++) {
        int s = i * 256 + threadIdx.x;
        float x = row[s];
        x = (s <= t) ? x * scale : 0.f;
        v[i] = x;
        sum += x;
    }
    __shared__ float red[32];
    #pragma unroll
    for (int o = 16; o; o >>= 1) sum += __shfl_xor_sync(0xffffffffu, sum, o);
    if ((threadIdx.x & 31) == 0) red[threadIdx.x >> 5] = sum;
    __syncthreads();
    if (threadIdx.x < 32) {
        float x = (threadIdx.x < 8) ? red[threadIdx.x] : 0.f;
        #pragma unroll
        for (int o = 4; o; o >>= 1) x += __shfl_xor_sync(0xffffffffu, x, o);
        if (threadIdx.x == 0) red[0] = x;
    }
    __syncthreads();
    float inv = 1.f / (red[0] + 1e-8f);
    #pragma unroll
    for (int i = 0; i < 8; i++)
        row[i * 256 + threadIdx.x] = v[i] * inv;
}

__global__ void swiglu_kernel(float* __restrict__ a, const float* __restrict__ b)
{
    long long i = (long long)blockIdx.x * blockDim.x + threadIdx.x;
    if (i < (long long)T_SEQ * INTER) {
        float x = a[i];
        float sig = 1.f / (1.f + expf(-x));
        a[i] = x * sig * b[i];
    }
}

// ---------------- orchestration ---------------------------------------------
extern "C" void kernel_launch(void* const* d_in, const int* in_sizes, int n_in,
                              void* d_out, int out_size)
{
    const int*   idx       = (const int*)  d_in[0];
    const float* wte       = (const float*)d_in[1];
    const float* attn_w    = (const float*)d_in[2];
    const float* proj_w    = (const float*)d_in[3];
    const float* w1        = (const float*)d_in[4];
    const float* w2        = (const float*)d_in[5];
    const float* w3        = (const float*)d_in[6];
    const float* norm1_w   = (const float*)d_in[7];
    const float* norm2_w   = (const float*)d_in[8];
    const float* ln_f_w    = (const float*)d_in[9];
    const float* lm_head_w = (const float*)d_in[10];
    float* out = (float*)d_out;

    float *x, *n, *qkv, *q, *k, *vT, *S, *y, *h1, *h2;
    cudaGetSymbolAddress((void**)&x,   g_x);
    cudaGetSymbolAddress((void**)&n,   g_n);
    cudaGetSymbolAddress((void**)&qkv, g_qkv);
    cudaGetSymbolAddress((void**)&q,   g_q);
    cudaGetSymbolAddress((void**)&k,   g_k);
    cudaGetSymbolAddress((void**)&vT,  g_vT);
    cudaGetSymbolAddress((void**)&S,   g_S);
    cudaGetSymbolAddress((void**)&y,   g_y);
    cudaGetSymbolAddress((void**)&h1,  g_h1);
    cudaGetSymbolAddress((void**)&h2,  g_h2);

    const int SMEM = 2 * STGW * 4;   // 2 stages * 10240 words * 4B = 81920 B
    cudaFuncSetAttribute(gemm_f16, cudaFuncAttributeMaxDynamicSharedMemorySize, SMEM);

    const long long TT = (long long)T_SEQ * T_SEQ;
    const long long TH = (long long)T_SEQ * HEAD_SIZE;

    embed_kernel<<<T_SEQ, 256>>>(idx, wte, x);

    for (int l = 0; l < 2; l++) {
        const float* aw  = attn_w + (long long)l * QKV_DIM * N_EMBD;
        const float* pw  = proj_w + (long long)l * N_EMBD * N_EMBD;
        const float* w1l = w1 + (long long)l * INTER * N_EMBD;
        const float* w2l = w2 + (long long)l * INTER * N_EMBD;
        const float* w3l = w3 + (long long)l * N_EMBD * INTER;

        rmsnorm_kernel<<<T_SEQ, 256>>>(x, norm1_w + l * N_EMBD, n);

        // qkv = n1 @ attn_w^T
        gemm_f16<<<dim3(T_SEQ / BMT, QKV_DIM / BNT, 1), 256, SMEM>>>(
            n, N_EMBD, 0, aw, N_EMBD, 0, 1,
            qkv, QKV_DIM, 0, nullptr, N_EMBD, 0);

        qkv_post_kernel<<<T_SEQ, 512>>>(qkv, q, k, vT);

        // S[h] = q[h] @ k[g]^T  (causal tile skip)
        gemm_f16<<<dim3(T_SEQ / BMT, T_SEQ / BNT, N_HEADS), 256, SMEM>>>(
            q, HEAD_SIZE, TH, k, HEAD_SIZE, TH, 4,
            S, T_SEQ, TT, nullptr, HEAD_SIZE, 1);

        attn_norm_kernel<<<dim3(T_SEQ, N_HEADS), 256>>>(S);

        // y[:, h] = P[h] @ vT[g]^T  (K clamped at diagonal)
        gemm_f16<<<dim3(T_SEQ / BMT, HEAD_SIZE / BNT, N_HEADS), 256, SMEM>>>(
            S, T_SEQ, TT, vT, T_SEQ, (long long)HEAD_SIZE * T_SEQ, 4,
            y, N_EMBD, HEAD_SIZE, nullptr, T_SEQ, 2);

        // x = x + y @ proj_w^T
        gemm_f16<<<dim3(T_SEQ / BMT, N_EMBD / BNT, 1), 256, SMEM>>>(
            y, N_EMBD, 0, pw, N_EMBD, 0, 1,
            x, N_EMBD, 0, x, N_EMBD, 0);

        rmsnorm_kernel<<<T_SEQ, 256>>>(x, norm2_w + l * N_EMBD, n);

        gemm_f16<<<dim3(T_SEQ / BMT, INTER / BNT, 1), 256, SMEM>>>(
            n, N_EMBD, 0, w1l, N_EMBD, 0, 1,
            h1, INTER, 0, nullptr, N_EMBD, 0);
        gemm_f16<<<dim3(T_SEQ / BMT, INTER / BNT, 1), 256, SMEM>>>(
            n, N_EMBD, 0, w2l, N_EMBD, 0, 1,
            h2, INTER, 0, nullptr, N_EMBD, 0);

        swiglu_kernel<<<(T_SEQ * INTER) / 256, 256>>>(h1, h2);

        // x = x + h @ w3^T
        gemm_f16<<<dim3(T_SEQ / BMT, N_EMBD / BNT, 1), 256, SMEM>>>(
            h1, INTER, 0, w3l, INTER, 0, 1,
            x, N_EMBD, 0, x, INTER, 0);
    }

    rmsnorm_kernel<<<T_SEQ, 256>>>(x, ln_f_w, n);
    gemm_f16<<<dim3(T_SEQ / BMT, VOCAB / BNT, 1), 256, SMEM>>>(
        n, N_EMBD, 0, lm_head_w, N_EMBD, 0, 1,
        out, VOCAB, 0, nullptr, N_EMBD, 0);
}

// round 5
// speedup vs baseline: 2.7668x; 1.0411x over previous
#include <cuda_runtime.h>
#include <cuda_fp16.h>
#include <math.h>
#include <stdint.h>

#define T_SEQ 2048
#define N_EMBD 2048
#define N_HEADS 16
#define N_GROUPS 4
#define HEAD_SIZE 128
#define INTER 5632
#define VOCAB 32000
#define QKV_DIM 3072

// ---------------- scratch ---------------------------------------------------
__device__ float g_x  [T_SEQ * N_EMBD];
__device__ float g_n  [T_SEQ * N_EMBD];
__device__ float g_qkv[T_SEQ * QKV_DIM];
__device__ float g_q  [N_HEADS  * T_SEQ * HEAD_SIZE];
__device__ float g_k  [N_GROUPS * T_SEQ * HEAD_SIZE];
__device__ float g_vT [N_GROUPS * HEAD_SIZE * T_SEQ];
__device__ float g_S  [N_HEADS * T_SEQ * T_SEQ];
__device__ float g_y  [T_SEQ * N_EMBD];
__device__ float g_h1 [T_SEQ * INTER];
__device__ float g_h2 [T_SEQ * INTER];

// ---------------- helpers ---------------------------------------------------
__device__ __forceinline__ uint32_t cvta_smem(const void* p) {
    uint32_t a;
    asm("{.reg .u64 t; cvta.to.shared.u64 t, %1; cvt.u32.u64 %0, t;}" : "=r"(a) : "l"(p));
    return a;
}

__device__ __forceinline__ void mma16(float* d, const uint32_t* a, const uint32_t* b) {
    asm volatile(
        "mma.sync.aligned.m16n8k16.row.col.f32.f16.f16.f32 "
        "{%0,%1,%2,%3}, {%4,%5,%6,%7}, {%8,%9}, {%0,%1,%2,%3};"
        : "+f"(d[0]), "+f"(d[1]), "+f"(d[2]), "+f"(d[3])
        : "r"(a[0]), "r"(a[1]), "r"(a[2]), "r"(a[3]), "r"(b[0]), "r"(b[1]));
}

__device__ __forceinline__ void ldsm4(uint32_t* r, uint32_t addr) {
    asm volatile("ldmatrix.sync.aligned.m8n8.x4.shared.b16 {%0,%1,%2,%3}, [%4];"
        : "=r"(r[0]), "=r"(r[1]), "=r"(r[2]), "=r"(r[3]) : "r"(addr));
}

// split float4 -> hi half2x2 + lo half2x2
__device__ __forceinline__ void split4(float4 v, uint2& hi, uint2& lo) {
    __half2 h01 = __floats2half2_rn(v.x, v.y);
    __half2 h23 = __floats2half2_rn(v.z, v.w);
    float2 f01 = __half22float2(h01);
    float2 f23 = __half22float2(h23);
    __half2 l01 = __floats2half2_rn(v.x - f01.x, v.y - f01.y);
    __half2 l23 = __floats2half2_rn(v.z - f23.x, v.w - f23.y);
    hi.x = *(uint32_t*)&h01; hi.y = *(uint32_t*)&h23;
    lo.x = *(uint32_t*)&l01; lo.y = *(uint32_t*)&l23;
}

// ---------------- fp16x3 NT GEMM (mma.sync m16n8k16 + ldmatrix) -------------
// C[m,n] = sum_k A[m,k]*B[n,k]; fp32 in gmem, split to f16 hi/lo in-kernel.
// mode: 0 plain, 1 causal tile skip (S), 2 causal K-clamp (PV)
#define BMT 128
#define BNT 128
#define KB  32
#define ROWW 20                    // 32-bit words per smem row (40 halves, padded)
#define SUBW (128 * ROWW)          // words per sub-tile
#define STGW (4 * SUBW)            // words per stage (Ahi,Alo,Bhi,Blo)

__global__ void __launch_bounds__(256)
gemm_f16(const float* __restrict__ A, int lda, long long sA,
         const float* __restrict__ B, int ldb, long long sB, int bdiv,
         float* C, int ldc, long long sC,
         const float* __restrict__ addC,
         int K, int mode)
{
    extern __shared__ __align__(16) uint32_t smw[];
    const int m0 = blockIdx.x * BMT;
    const int n0 = blockIdx.y * BNT;
    if (mode == 1 && n0 > m0 + BMT - 1) return;
    const int Keff = (mode == 2) ? min(K, m0 + BMT) : K;
    const int KT = Keff / KB;
    const int z = blockIdx.z;
    A += (long long)z * sA;
    B += (long long)(z / bdiv) * sB;
    const long long coff = (long long)z * sC;

    const int tid  = threadIdx.x;
    const int lane = tid & 31;
    const int wid  = tid >> 5;
    const int wm   = (wid & 1) * 64;
    const int wn   = (wid >> 1) * 32;
    const uint32_t sbase = cvta_smem(smw);

    // ldmatrix per-lane address components (words)
    const int aRow  = wm + (lane & 15);
    const int aCol4 = (lane & 16) ? 4 : 0;
    const int bRow  = wn + (lane & 7) + ((lane & 16) ? 8 : 0);
    const int bCol4 = (lane & 8) ? 4 : 0;

    // register staging for one K-tile
    float4 rA[4], rB[4];
    const int lr = tid >> 3;
    const int lc = tid & 7;

    auto ldg_tile = [&](int kt) {
        #pragma unroll
        for (int it = 0; it < 4; it++) {
            int r = it * 32 + lr;
            rA[it] = *(const float4*)(A + (long long)(m0 + r) * lda + kt * KB + lc * 4);
            rB[it] = *(const float4*)(B + (long long)(n0 + r) * ldb + kt * KB + lc * 4);
        }
    };
    auto sts_tile = [&](int s) {
        uint32_t* st = smw + s * STGW;
        #pragma unroll
        for (int it = 0; it < 4; it++) {
            int r = it * 32 + lr;
            int w = r * ROWW + lc * 2;
            uint2 hi, lo;
            split4(rA[it], hi, lo);
            *(uint2*)(st + w) = hi;
            *(uint2*)(st + SUBW + w) = lo;
            split4(rB[it], hi, lo);
            *(uint2*)(st + 2 * SUBW + w) = hi;
            *(uint2*)(st + 3 * SUBW + w) = lo;
        }
    };

    float acc[4][4][4];
    #pragma unroll
    for (int a = 0; a < 4; a++)
        #pragma unroll
        for (int b = 0; b < 4; b++)
            #pragma unroll
            for (int c = 0; c < 4; c++) acc[a][b][c] = 0.f;

    ldg_tile(0);
    sts_tile(0);
    if (KT > 1) ldg_tile(1);
    __syncthreads();

    for (int kt = 0; kt < KT; kt++) {
        if (kt + 1 < KT) sts_tile((kt + 1) & 1);
        if (kt + 2 < KT) ldg_tile(kt + 2);

        const uint32_t stAddr = sbase + (uint32_t)((kt & 1) * STGW) * 4u;

        #pragma unroll
        for (int ks = 0; ks < 2; ks++) {
            uint32_t Ah[4][4], Al[4][4], Bh[4][2], Bl[4][2];
            #pragma unroll
            for (int mc = 0; mc < 4; mc++) {
                uint32_t off = stAddr + (uint32_t)(((aRow + mc * 16) * ROWW + aCol4 + ks * 8)) * 4u;
                ldsm4(Ah[mc], off);
                ldsm4(Al[mc], off + SUBW * 4u);
            }
            #pragma unroll
            for (int ncp = 0; ncp < 2; ncp++) {
                uint32_t off = stAddr + (uint32_t)((2 * SUBW + (bRow + ncp * 16) * ROWW + bCol4 + ks * 8)) * 4u;
                uint32_t t[4];
                ldsm4(t, off);
                Bh[ncp * 2][0] = t[0]; Bh[ncp * 2][1] = t[1];
                Bh[ncp * 2 + 1][0] = t[2]; Bh[ncp * 2 + 1][1] = t[3];
                ldsm4(t, off + SUBW * 4u);
                Bl[ncp * 2][0] = t[0]; Bl[ncp * 2][1] = t[1];
                Bl[ncp * 2 + 1][0] = t[2]; Bl[ncp * 2 + 1][1] = t[3];
            }
            #pragma unroll
            for (int mc = 0; mc < 4; mc++)
                #pragma unroll
                for (int nc = 0; nc < 4; nc++) {
                    mma16(acc[mc][nc], Ah[mc], Bh[nc]);
                    mma16(acc[mc][nc], Ah[mc], Bl[nc]);
                    mma16(acc[mc][nc], Al[mc], Bh[nc]);
                }
        }
        __syncthreads();
    }

    // ---- epilogue: registers -> gmem (float2, coalesced) ----
    #pragma unroll
    for (int mc = 0; mc < 4; mc++)
        #pragma unroll
        for (int nc = 0; nc < 4; nc++) {
            int c0 = n0 + wn + nc * 8 + (lane & 3) * 2;
            #pragma unroll
            for (int rr = 0; rr < 2; rr++) {
                int row = m0 + wm + mc * 16 + (lane >> 2) + rr * 8;
                float v0 = acc[mc][nc][rr * 2];
                float v1 = acc[mc][nc][rr * 2 + 1];
                long long off = coff + (long long)row * ldc + c0;
                if (addC) { v0 += addC[off]; v1 += addC[off + 1]; }
                C[off] = v0;
                C[off + 1] = v1;
            }
        }
}

// ---------------- elementwise kernels ---------------------------------------
__global__ void embed_kernel(const int* __restrict__ idx,
                             const float* __restrict__ wte, float* __restrict__ x)
{
    int t = blockIdx.x;
    const float* src = wte + (long long)idx[t] * N_EMBD;
    float* dst = x + (long long)t * N_EMBD;
    for (int e = threadIdx.x; e < N_EMBD; e += blockDim.x) dst[e] = src[e];
}

__global__ void rmsnorm_kernel(const float* __restrict__ x, const float* __restrict__ w,
                               float* __restrict__ out)
{
    int t = blockIdx.x;
    const float* row = x + (long long)t * N_EMBD;
    float s = 0.f;
    for (int e = threadIdx.x; e < N_EMBD; e += blockDim.x) { float v = row[e]; s += v * v; }
    __shared__ float red[32];
    #pragma unroll
    for (int o = 16; o; o >>= 1) s += __shfl_xor_sync(0xffffffffu, s, o);
    if ((threadIdx.x & 31) == 0) red[threadIdx.x >> 5] = s;
    __syncthreads();
    if (threadIdx.x < 32) {
        float v = (threadIdx.x < (blockDim.x >> 5)) ? red[threadIdx.x] : 0.f;
        #pragma unroll
        for (int o = 16; o; o >>= 1) v += __shfl_xor_sync(0xffffffffu, v, o);
        if (threadIdx.x == 0) red[0] = v;
    }
    __syncthreads();
    float r = rsqrtf(red[0] * (1.f / N_EMBD) + 1e-5f);
    float* dst = out + (long long)t * N_EMBD;
    for (int e = threadIdx.x; e < N_EMBD; e += blockDim.x)
        dst[e] = row[e] * r * w[e];
}

__global__ void qkv_post_kernel(const float* __restrict__ qkv,
                                float* __restrict__ q,
                                float* __restrict__ k,
                                float* __restrict__ vT)
{
    int t = blockIdx.x;
    const float LN_BASE = 9.210340371976184f;
    for (int i = threadIdx.x; i < N_GROUPS * 6 * 64; i += blockDim.x) {
        int j    = i & 63;
        int slot = (i >> 6) % 6;
        int g    = i / (6 * 64);
        const float* src = qkv + (long long)t * QKV_DIM + (g * 6 + slot) * HEAD_SIZE;
        float x1 = src[j];
        float x2 = src[j + 64];
        if (slot < 5) {
            float theta = expf(-(2.f * j / 128.f) * LN_BASE);
            float ang = (float)t * theta;
            float sv, cv;
            sincosf(ang, &sv, &cv);
            float o1 = x1 * cv - x2 * sv;
            float o2 = x1 * sv + x2 * cv;
            o1 = (o1 > 0.f) ? (o1 + 1.f) : expf(o1);
            o2 = (o2 > 0.f) ? (o2 + 1.f) : expf(o2);
            if (slot < 4) {
                int h = g * 4 + slot;
                float* dst = q + ((long long)h * T_SEQ + t) * HEAD_SIZE;
                dst[j] = o1; dst[j + 64] = o2;
            } else {
                float* dst = k + ((long long)g * T_SEQ + t) * HEAD_SIZE;
                dst[j] = o1; dst[j + 64] = o2;
            }
        } else {
            vT[((long long)g * HEAD_SIZE + j) * T_SEQ + t]      = x1;
            vT[((long long)g * HEAD_SIZE + j + 64) * T_SEQ + t] = x2;
        }
    }
}

__global__ void __launch_bounds__(256)
attn_norm_kernel(float* __restrict__ S)
{
    int t = blockIdx.x;
    int h = blockIdx.y;
    float* row = S + ((long long)h * T_SEQ + t) * T_SEQ;
    const float scale = 0.08838834764831845f;
    float v[8];
    float sum = 0.f;
    #pragma unroll
    for (int i = 0; i < 8; i++) {
        int s = i * 256 + threadIdx.x;
        float x = row[s];
        x = (s <= t) ? x * scale : 0.f;
        v[i] = x;
        sum += x;
    }
    __shared__ float red[32];
    #pragma unroll
    for (int o = 16; o; o >>= 1) sum += __shfl_xor_sync(0xffffffffu, sum, o);
    if ((threadIdx.x & 31) == 0) red[threadIdx.x >> 5] = sum;
    __syncthreads();
    if (threadIdx.x < 32) {
        float x = (threadIdx.x < 8) ? red[threadIdx.x] : 0.f;
        #pragma unroll
        for (int o = 4; o; o >>= 1) x += __shfl_xor_sync(0xffffffffu, x, o);
        if (threadIdx.x == 0) red[0] = x;
    }
    __syncthreads();
    float inv = 1.f / (red[0] + 1e-8f);
    #pragma unroll
    for (int i = 0; i < 8; i++)
        row[i * 256 + threadIdx.x] = v[i] * inv;
}

__global__ void swiglu_kernel(float* __restrict__ a, const float* __restrict__ b)
{
    long long i = (long long)blockIdx.x * blockDim.x + threadIdx.x;
    if (i < (long long)T_SEQ * INTER) {
        float x = a[i];
        float sig = 1.f / (1.f + expf(-x));
        a[i] = x * sig * b[i];
    }
}

// ---------------- orchestration ---------------------------------------------
extern "C" void kernel_launch(void* const* d_in, const int* in_sizes, int n_in,
                              void* d_out, int out_size)
{
    const int*   idx       = (const int*)  d_in[0];
    const float* wte       = (const float*)d_in[1];
    const float* attn_w    = (const float*)d_in[2];
    const float* proj_w    = (const float*)d_in[3];
    const float* w1        = (const float*)d_in[4];
    const float* w2        = (const float*)d_in[5];
    const float* w3        = (const float*)d_in[6];
    const float* norm1_w   = (const float*)d_in[7];
    const float* norm2_w   = (const float*)d_in[8];
    const float* ln_f_w    = (const float*)d_in[9];
    const float* lm_head_w = (const float*)d_in[10];
    float* out = (float*)d_out;

    float *x, *n, *qkv, *q, *k, *vT, *S, *y, *h1, *h2;
    cudaGetSymbolAddress((void**)&x,   g_x);
    cudaGetSymbolAddress((void**)&n,   g_n);
    cudaGetSymbolAddress((void**)&qkv, g_qkv);
    cudaGetSymbolAddress((void**)&q,   g_q);
    cudaGetSymbolAddress((void**)&k,   g_k);
    cudaGetSymbolAddress((void**)&vT,  g_vT);
    cudaGetSymbolAddress((void**)&S,   g_S);
    cudaGetSymbolAddress((void**)&y,   g_y);
    cudaGetSymbolAddress((void**)&h1,  g_h1);
    cudaGetSymbolAddress((void**)&h2,  g_h2);

    const int SMEM = 2 * STGW * 4;   // 81920 B
    cudaFuncSetAttribute(gemm_f16, cudaFuncAttributeMaxDynamicSharedMemorySize, SMEM);

    const long long TT = (long long)T_SEQ * T_SEQ;
    const long long TH = (long long)T_SEQ * HEAD_SIZE;

    embed_kernel<<<T_SEQ, 256>>>(idx, wte, x);

    for (int l = 0; l < 2; l++) {
        const float* aw  = attn_w + (long long)l * QKV_DIM * N_EMBD;
        const float* pw  = proj_w + (long long)l * N_EMBD * N_EMBD;
        const float* w1l = w1 + (long long)l * INTER * N_EMBD;
        const float* w2l = w2 + (long long)l * INTER * N_EMBD;
        const float* w3l = w3 + (long long)l * N_EMBD * INTER;

        rmsnorm_kernel<<<T_SEQ, 256>>>(x, norm1_w + l * N_EMBD, n);

        // qkv = n1 @ attn_w^T
        gemm_f16<<<dim3(T_SEQ / BMT, QKV_DIM / BNT, 1), 256, SMEM>>>(
            n, N_EMBD, 0, aw, N_EMBD, 0, 1,
            qkv, QKV_DIM, 0, nullptr, N_EMBD, 0);

        qkv_post_kernel<<<T_SEQ, 512>>>(qkv, q, k, vT);

        // S[h] = q[h] @ k[g]^T  (causal tile skip)
        gemm_f16<<<dim3(T_SEQ / BMT, T_SEQ / BNT, N_HEADS), 256, SMEM>>>(
            q, HEAD_SIZE, TH, k, HEAD_SIZE, TH, 4,
            S, T_SEQ, TT, nullptr, HEAD_SIZE, 1);

        attn_norm_kernel<<<dim3(T_SEQ, N_HEADS), 256>>>(S);

        // y[:, h] = P[h] @ vT[g]^T  (K clamped at diagonal)
        gemm_f16<<<dim3(T_SEQ / BMT, HEAD_SIZE / BNT, N_HEADS), 256, SMEM>>>(
            S, T_SEQ, TT, vT, T_SEQ, (long long)HEAD_SIZE * T_SEQ, 4,
            y, N_EMBD, HEAD_SIZE, nullptr, T_SEQ, 2);

        // x = x + y @ proj_w^T
        gemm_f16<<<dim3(T_SEQ / BMT, N_EMBD / BNT, 1), 256, SMEM>>>(
            y, N_EMBD, 0, pw, N_EMBD, 0, 1,
            x, N_EMBD, 0, x, N_EMBD, 0);

        rmsnorm_kernel<<<T_SEQ, 256>>>(x, norm2_w + l * N_EMBD, n);

        gemm_f16<<<dim3(T_SEQ / BMT, INTER / BNT, 1), 256, SMEM>>>(
            n, N_EMBD, 0, w1l, N_EMBD, 0, 1,
            h1, INTER, 0, nullptr, N_EMBD, 0);
        gemm_f16<<<dim3(T_SEQ / BMT, INTER / BNT, 1), 256, SMEM>>>(
            n, N_EMBD, 0, w2l, N_EMBD, 0, 1,
            h2, INTER, 0, nullptr, N_EMBD, 0);

        swiglu_kernel<<<(T_SEQ * INTER) / 256, 256>>>(h1, h2);

        // x = x + h @ w3^T
        gemm_f16<<<dim3(T_SEQ / BMT, N_EMBD / BNT, 1), 256, SMEM>>>(
            h1, INTER, 0, w3l, INTER, 0, 1,
            x, N_EMBD, 0, x, INTER, 0);
    }

    rmsnorm_kernel<<<T_SEQ, 256>>>(x, ln_f_w, n);
    gemm_f16<<<dim3(T_SEQ / BMT, VOCAB / BNT, 1), 256, SMEM>>>(
        n, N_EMBD, 0, lm_head_w, N_EMBD, 0, 1,
        out, VOCAB, 0, nullptr, N_EMBD, 0);
}

// round 6
// speedup vs baseline: 3.3621x; 1.2152x over previous
#include <cuda_runtime.h>
#include <cuda_fp16.h>
#include <math.h>
#include <stdint.h>

#define T_SEQ 2048
#define N_EMBD 2048
#define N_HEADS 16
#define N_GROUPS 4
#define HEAD_SIZE 128
#define INTER 5632
#define VOCAB 32000
#define QKV_DIM 3072

// ---------------- scratch ---------------------------------------------------
__device__ float g_x  [T_SEQ * N_EMBD];
__device__ float g_n  [T_SEQ * N_EMBD];
__device__ float g_qkv[T_SEQ * QKV_DIM];
__device__ float g_q  [N_HEADS  * T_SEQ * HEAD_SIZE];
__device__ float g_k  [N_GROUPS * T_SEQ * HEAD_SIZE];
__device__ float g_vT [N_GROUPS * HEAD_SIZE * T_SEQ];
__device__ float g_S  [N_HEADS * T_SEQ * T_SEQ];
__device__ float g_y  [T_SEQ * N_EMBD];
__device__ float g_h1 [T_SEQ * INTER];
__device__ float g_h2 [T_SEQ * INTER];

// ---------------- helpers ---------------------------------------------------
__device__ __forceinline__ uint32_t cvta_smem(const void* p) {
    uint32_t a;
    asm("{.reg .u64 t; cvta.to.shared.u64 t, %1; cvt.u32.u64 %0, t;}" : "=r"(a) : "l"(p));
    return a;
}

__device__ __forceinline__ void mma16(float* d, const uint32_t* a, const uint32_t* b) {
    asm volatile(
        "mma.sync.aligned.m16n8k16.row.col.f32.f16.f16.f32 "
        "{%0,%1,%2,%3}, {%4,%5,%6,%7}, {%8,%9}, {%0,%1,%2,%3};"
        : "+f"(d[0]), "+f"(d[1]), "+f"(d[2]), "+f"(d[3])
        : "r"(a[0]), "r"(a[1]), "r"(a[2]), "r"(a[3]), "r"(b[0]), "r"(b[1]));
}

__device__ __forceinline__ void ldsm4(uint32_t* r, uint32_t addr) {
    asm volatile("ldmatrix.sync.aligned.m8n8.x4.shared.b16 {%0,%1,%2,%3}, [%4];"
        : "=r"(r[0]), "=r"(r[1]), "=r"(r[2]), "=r"(r[3]) : "r"(addr));
}

// split float4 -> hi half2x2 + lo half2x2
__device__ __forceinline__ void split4(float4 v, uint2& hi, uint2& lo) {
    __half2 h01 = __floats2half2_rn(v.x, v.y);
    __half2 h23 = __floats2half2_rn(v.z, v.w);
    float2 f01 = __half22float2(h01);
    float2 f23 = __half22float2(h23);
    __half2 l01 = __floats2half2_rn(v.x - f01.x, v.y - f01.y);
    __half2 l23 = __floats2half2_rn(v.z - f23.x, v.w - f23.y);
    hi.x = *(uint32_t*)&h01; hi.y = *(uint32_t*)&h23;
    lo.x = *(uint32_t*)&l01; lo.y = *(uint32_t*)&l23;
}
__device__ __forceinline__ void trunc4(float4 v, uint2& hi) {
    __half2 h01 = __floats2half2_rn(v.x, v.y);
    __half2 h23 = __floats2half2_rn(v.z, v.w);
    hi.x = *(uint32_t*)&h01; hi.y = *(uint32_t*)&h23;
}

// ---------------- fp16 split NT GEMM (mma.sync m16n8k16 + ldmatrix) ---------
// C[m,n] = sum_k A[m,k]*B[n,k]; fp32 in gmem, split to f16 in-kernel.
// SPLITB=1: A=Ah+Al, B=Bh+Bl, 3 MMAs (AhBh+AhBl+AlBh).
// SPLITB=0: A=Ah+Al, B=Bh (truncated), 2 MMAs (AhBh+AlBh).
// mode: 0 plain, 1 causal tile skip (S), 2 causal K-clamp (PV)
#define BMT 128
#define BNT 128
#define KB  32
#define ROWW 20                    // 32-bit words per smem row (40 halves, padded)
#define SUBW (128 * ROWW)          // words per sub-tile

template<int SPLITB>
__global__ void __launch_bounds__(256)
gemm_f16(const float* __restrict__ A, int lda, long long sA,
         const float* __restrict__ B, int ldb, long long sB, int bdiv,
         float* C, int ldc, long long sC,
         const float* __restrict__ addC,
         int K, int mode)
{
    constexpr int NSUB = 3 + SPLITB;          // subtiles per stage
    constexpr int STGW = NSUB * SUBW;
    extern __shared__ __align__(16) uint32_t smw[];
    const int m0 = blockIdx.x * BMT;
    const int n0 = blockIdx.y * BNT;
    if (mode == 1 && n0 > m0 + BMT - 1) return;
    const int Keff = (mode == 2) ? min(K, m0 + BMT) : K;
    const int KT = Keff / KB;
    const int z = blockIdx.z;
    A += (long long)z * sA;
    B += (long long)(z / bdiv) * sB;
    const long long coff = (long long)z * sC;

    const int tid  = threadIdx.x;
    const int lane = tid & 31;
    const int wid  = tid >> 5;
    const int wm   = (wid & 1) * 64;
    const int wn   = (wid >> 1) * 32;
    const uint32_t sbase = cvta_smem(smw);

    // ldmatrix per-lane address components (words)
    const int aRow  = wm + (lane & 15);
    const int aCol4 = (lane & 16) ? 4 : 0;
    const int bRow  = wn + (lane & 7) + ((lane & 16) ? 8 : 0);
    const int bCol4 = (lane & 8) ? 4 : 0;

    // register staging for one K-tile
    float4 rA[4], rB[4];
    const int lr = tid >> 3;
    const int lc = tid & 7;

    auto ldg_tile = [&](int kt) {
        #pragma unroll
        for (int it = 0; it < 4; it++) {
            int r = it * 32 + lr;
            rA[it] = *(const float4*)(A + (long long)(m0 + r) * lda + kt * KB + lc * 4);
            rB[it] = *(const float4*)(B + (long long)(n0 + r) * ldb + kt * KB + lc * 4);
        }
    };
    auto sts_tile = [&](int s) {
        uint32_t* st = smw + s * STGW;
        #pragma unroll
        for (int it = 0; it < 4; it++) {
            int r = it * 32 + lr;
            int w = r * ROWW + lc * 2;
            uint2 hi, lo;
            split4(rA[it], hi, lo);
            *(uint2*)(st + w) = hi;
            *(uint2*)(st + SUBW + w) = lo;
            if (SPLITB) {
                split4(rB[it], hi, lo);
                *(uint2*)(st + 2 * SUBW + w) = hi;
                *(uint2*)(st + 3 * SUBW + w) = lo;
            } else {
                trunc4(rB[it], hi);
                *(uint2*)(st + 2 * SUBW + w) = hi;
            }
        }
    };

    float acc[4][4][4];
    #pragma unroll
    for (int a = 0; a < 4; a++)
        #pragma unroll
        for (int b = 0; b < 4; b++)
            #pragma unroll
            for (int c = 0; c < 4; c++) acc[a][b][c] = 0.f;

    ldg_tile(0);
    sts_tile(0);
    if (KT > 1) ldg_tile(1);
    __syncthreads();

    for (int kt = 0; kt < KT; kt++) {
        if (kt + 1 < KT) sts_tile((kt + 1) & 1);
        if (kt + 2 < KT) ldg_tile(kt + 2);

        const uint32_t stAddr = sbase + (uint32_t)((kt & 1) * STGW) * 4u;

        #pragma unroll
        for (int ks = 0; ks < 2; ks++) {
            uint32_t Ah[4][4], Al[4][4], Bh[4][2], Bl[4][2];
            #pragma unroll
            for (int mc = 0; mc < 4; mc++) {
                uint32_t off = stAddr + (uint32_t)(((aRow + mc * 16) * ROWW + aCol4 + ks * 8)) * 4u;
                ldsm4(Ah[mc], off);
                ldsm4(Al[mc], off + SUBW * 4u);
            }
            #pragma unroll
            for (int ncp = 0; ncp < 2; ncp++) {
                uint32_t off = stAddr + (uint32_t)((2 * SUBW + (bRow + ncp * 16) * ROWW + bCol4 + ks * 8)) * 4u;
                uint32_t t[4];
                ldsm4(t, off);
                Bh[ncp * 2][0] = t[0]; Bh[ncp * 2][1] = t[1];
                Bh[ncp * 2 + 1][0] = t[2]; Bh[ncp * 2 + 1][1] = t[3];
                if (SPLITB) {
                    ldsm4(t, off + SUBW * 4u);
                    Bl[ncp * 2][0] = t[0]; Bl[ncp * 2][1] = t[1];
                    Bl[ncp * 2 + 1][0] = t[2]; Bl[ncp * 2 + 1][1] = t[3];
                }
            }
            #pragma unroll
            for (int mc = 0; mc < 4; mc++)
                #pragma unroll
                for (int nc = 0; nc < 4; nc++) {
                    mma16(acc[mc][nc], Ah[mc], Bh[nc]);
                    if (SPLITB) mma16(acc[mc][nc], Ah[mc], Bl[nc]);
                    mma16(acc[mc][nc], Al[mc], Bh[nc]);
                }
        }
        __syncthreads();
    }

    // ---- epilogue: registers -> gmem (float2, coalesced) ----
    #pragma unroll
    for (int mc = 0; mc < 4; mc++)
        #pragma unroll
        for (int nc = 0; nc < 4; nc++) {
            int c0 = n0 + wn + nc * 8 + (lane & 3) * 2;
            #pragma unroll
            for (int rr = 0; rr < 2; rr++) {
                int row = m0 + wm + mc * 16 + (lane >> 2) + rr * 8;
                float v0 = acc[mc][nc][rr * 2];
                float v1 = acc[mc][nc][rr * 2 + 1];
                long long off = coff + (long long)row * ldc + c0;
                if (addC) { v0 += addC[off]; v1 += addC[off + 1]; }
                C[off] = v0;
                C[off + 1] = v1;
            }
        }
}

// ---------------- elementwise kernels ---------------------------------------
__global__ void embed_kernel(const int* __restrict__ idx,
                             const float* __restrict__ wte, float* __restrict__ x)
{
    int t = blockIdx.x;
    const float* src = wte + (long long)idx[t] * N_EMBD;
    float* dst = x + (long long)t * N_EMBD;
    for (int e = threadIdx.x; e < N_EMBD; e += blockDim.x) dst[e] = src[e];
}

__global__ void rmsnorm_kernel(const float* __restrict__ x, const float* __restrict__ w,
                               float* __restrict__ out)
{
    int t = blockIdx.x;
    const float* row = x + (long long)t * N_EMBD;
    float s = 0.f;
    for (int e = threadIdx.x; e < N_EMBD; e += blockDim.x) { float v = row[e]; s += v * v; }
    __shared__ float red[32];
    #pragma unroll
    for (int o = 16; o; o >>= 1) s += __shfl_xor_sync(0xffffffffu, s, o);
    if ((threadIdx.x & 31) == 0) red[threadIdx.x >> 5] = s;
    __syncthreads();
    if (threadIdx.x < 32) {
        float v = (threadIdx.x < (blockDim.x >> 5)) ? red[threadIdx.x] : 0.f;
        #pragma unroll
        for (int o = 16; o; o >>= 1) v += __shfl_xor_sync(0xffffffffu, v, o);
        if (threadIdx.x == 0) red[0] = v;
    }
    __syncthreads();
    float r = rsqrtf(red[0] * (1.f / N_EMBD) + 1e-5f);
    float* dst = out + (long long)t * N_EMBD;
    for (int e = threadIdx.x; e < N_EMBD; e += blockDim.x)
        dst[e] = row[e] * r * w[e];
}

__global__ void qkv_post_kernel(const float* __restrict__ qkv,
                                float* __restrict__ q,
                                float* __restrict__ k,
                                float* __restrict__ vT)
{
    int t = blockIdx.x;
    const float LN_BASE = 9.210340371976184f;
    for (int i = threadIdx.x; i < N_GROUPS * 6 * 64; i += blockDim.x) {
        int j    = i & 63;
        int slot = (i >> 6) % 6;
        int g    = i / (6 * 64);
        const float* src = qkv + (long long)t * QKV_DIM + (g * 6 + slot) * HEAD_SIZE;
        float x1 = src[j];
        float x2 = src[j + 64];
        if (slot < 5) {
            float theta = expf(-(2.f * j / 128.f) * LN_BASE);
            float ang = (float)t * theta;
            float sv, cv;
            sincosf(ang, &sv, &cv);
            float o1 = x1 * cv - x2 * sv;
            float o2 = x1 * sv + x2 * cv;
            o1 = (o1 > 0.f) ? (o1 + 1.f) : expf(o1);
            o2 = (o2 > 0.f) ? (o2 + 1.f) : expf(o2);
            if (slot < 4) {
                int h = g * 4 + slot;
                float* dst = q + ((long long)h * T_SEQ + t) * HEAD_SIZE;
                dst[j] = o1; dst[j + 64] = o2;
            } else {
                float* dst = k + ((long long)g * T_SEQ + t) * HEAD_SIZE;
                dst[j] = o1; dst[j + 64] = o2;
            }
        } else {
            vT[((long long)g * HEAD_SIZE + j) * T_SEQ + t]      = x1;
            vT[((long long)g * HEAD_SIZE + j + 64) * T_SEQ + t] = x2;
        }
    }
}

__global__ void __launch_bounds__(256)
attn_norm_kernel(float* __restrict__ S)
{
    int t = blockIdx.x;
    int h = blockIdx.y;
    float* row = S + ((long long)h * T_SEQ + t) * T_SEQ;
    const float scale = 0.08838834764831845f;
    float v[8];
    float sum = 0.f;
    #pragma unroll
    for (int i = 0; i < 8; i++) {
        int s = i * 256 + threadIdx.x;
        float x = row[s];
        x = (s <= t) ? x * scale : 0.f;
        v[i] = x;
        sum += x;
    }
    __shared__ float red[32];
    #pragma unroll
    for (int o = 16; o; o >>= 1) sum += __shfl_xor_sync(0xffffffffu, sum, o);
    if ((threadIdx.x & 31) == 0) red[threadIdx.x >> 5] = sum;
    __syncthreads();
    if (threadIdx.x < 32) {
        float x = (threadIdx.x < 8) ? red[threadIdx.x] : 0.f;
        #pragma unroll
        for (int o = 4; o; o >>= 1) x += __shfl_xor_sync(0xffffffffu, x, o);
        if (threadIdx.x == 0) red[0] = x;
    }
    __syncthreads();
    float inv = 1.f / (red[0] + 1e-8f);
    #pragma unroll
    for (int i = 0; i < 8; i++)
        row[i * 256 + threadIdx.x] = v[i] * inv;
}

__global__ void swiglu_kernel(float* __restrict__ a, const float* __restrict__ b)
{
    long long i = (long long)blockIdx.x * blockDim.x + threadIdx.x;
    if (i < (long long)T_SEQ * INTER) {
        float x = a[i];
        float sig = 1.f / (1.f + expf(-x));
        a[i] = x * sig * b[i];
    }
}

// ---------------- orchestration ---------------------------------------------
extern "C" void kernel_launch(void* const* d_in, const int* in_sizes, int n_in,
                              void* d_out, int out_size)
{
    const int*   idx       = (const int*)  d_in[0];
    const float* wte       = (const float*)d_in[1];
    const float* attn_w    = (const float*)d_in[2];
    const float* proj_w    = (const float*)d_in[3];
    const float* w1        = (const float*)d_in[4];
    const float* w2        = (const float*)d_in[5];
    const float* w3        = (const float*)d_in[6];
    const float* norm1_w   = (const float*)d_in[7];
    const float* norm2_w   = (const float*)d_in[8];
    const float* ln_f_w    = (const float*)d_in[9];
    const float* lm_head_w = (const float*)d_in[10];
    float* out = (float*)d_out;

    float *x, *n, *qkv, *q, *k, *vT, *S, *y, *h1, *h2;
    cudaGetSymbolAddress((void**)&x,   g_x);
    cudaGetSymbolAddress((void**)&n,   g_n);
    cudaGetSymbolAddress((void**)&qkv, g_qkv);
    cudaGetSymbolAddress((void**)&q,   g_q);
    cudaGetSymbolAddress((void**)&k,   g_k);
    cudaGetSymbolAddress((void**)&vT,  g_vT);
    cudaGetSymbolAddress((void**)&S,   g_S);
    cudaGetSymbolAddress((void**)&y,   g_y);
    cudaGetSymbolAddress((void**)&h1,  g_h1);
    cudaGetSymbolAddress((void**)&h2,  g_h2);

    const int SMEM3 = 2 * 4 * SUBW * 4;   // 81920 B (SPLITB=1)
    const int SMEM2 = 2 * 3 * SUBW * 4;   // 61440 B (SPLITB=0)
    cudaFuncSetAttribute(gemm_f16<1>, cudaFuncAttributeMaxDynamicSharedMemorySize, SMEM3);
    cudaFuncSetAttribute(gemm_f16<0>, cudaFuncAttributeMaxDynamicSharedMemorySize, SMEM2);

    const long long TT = (long long)T_SEQ * T_SEQ;
    const long long TH = (long long)T_SEQ * HEAD_SIZE;

    embed_kernel<<<T_SEQ, 256>>>(idx, wte, x);

    for (int l = 0; l < 2; l++) {
        const float* aw  = attn_w + (long long)l * QKV_DIM * N_EMBD;
        const float* pw  = proj_w + (long long)l * N_EMBD * N_EMBD;
        const float* w1l = w1 + (long long)l * INTER * N_EMBD;
        const float* w2l = w2 + (long long)l * INTER * N_EMBD;
        const float* w3l = w3 + (long long)l * N_EMBD * INTER;

        rmsnorm_kernel<<<T_SEQ, 256>>>(x, norm1_w + l * N_EMBD, n);

        // qkv = n1 @ attn_w^T  (3-term)
        gemm_f16<1><<<dim3(T_SEQ / BMT, QKV_DIM / BNT, 1), 256, SMEM3>>>(
            n, N_EMBD, 0, aw, N_EMBD, 0, 1,
            qkv, QKV_DIM, 0, nullptr, N_EMBD, 0);

        qkv_post_kernel<<<T_SEQ, 512>>>(qkv, q, k, vT);

        // S[h] = q[h] @ k[g]^T  (causal tile skip, 3-term)
        gemm_f16<1><<<dim3(T_SEQ / BMT, T_SEQ / BNT, N_HEADS), 256, SMEM3>>>(
            q, HEAD_SIZE, TH, k, HEAD_SIZE, TH, 4,
            S, T_SEQ, TT, nullptr, HEAD_SIZE, 1);

        attn_norm_kernel<<<dim3(T_SEQ, N_HEADS), 256>>>(S);

        // y[:, h] = P[h] @ vT[g]^T  (K clamped at diagonal, 3-term)
        gemm_f16<1><<<dim3(T_SEQ / BMT, HEAD_SIZE / BNT, N_HEADS), 256, SMEM3>>>(
            S, T_SEQ, TT, vT, T_SEQ, (long long)HEAD_SIZE * T_SEQ, 4,
            y, N_EMBD, HEAD_SIZE, nullptr, T_SEQ, 2);

        // x = x + y @ proj_w^T  (3-term)
        gemm_f16<1><<<dim3(T_SEQ / BMT, N_EMBD / BNT, 1), 256, SMEM3>>>(
            y, N_EMBD, 0, pw, N_EMBD, 0, 1,
            x, N_EMBD, 0, x, N_EMBD, 0);

        rmsnorm_kernel<<<T_SEQ, 256>>>(x, norm2_w + l * N_EMBD, n);

        // MLP: 2-term (weights truncated to fp16)
        gemm_f16<0><<<dim3(T_SEQ / BMT, INTER / BNT, 1), 256, SMEM2>>>(
            n, N_EMBD, 0, w1l, N_EMBD, 0, 1,
            h1, INTER, 0, nullptr, N_EMBD, 0);
        gemm_f16<0><<<dim3(T_SEQ / BMT, INTER / BNT, 1), 256, SMEM2>>>(
            n, N_EMBD, 0, w2l, N_EMBD, 0, 1,
            h2, INTER, 0, nullptr, N_EMBD, 0);

        swiglu_kernel<<<(T_SEQ * INTER) / 256, 256>>>(h1, h2);

        // x = x + h @ w3^T  (2-term)
        gemm_f16<0><<<dim3(T_SEQ / BMT, N_EMBD / BNT, 1), 256, SMEM2>>>(
            h1, INTER, 0, w3l, INTER, 0, 1,
            x, N_EMBD, 0, x, INTER, 0);
    }

    rmsnorm_kernel<<<T_SEQ, 256>>>(x, ln_f_w, n);
    // lm_head: 2-term
    gemm_f16<0><<<dim3(T_SEQ / BMT, VOCAB / BNT, 1), 256, SMEM2>>>(
        n, N_EMBD, 0, lm_head_w, N_EMBD, 0, 1,
        out, VOCAB, 0, nullptr, N_EMBD, 0);
}

// round 7
// speedup vs baseline: 3.7549x; 1.1168x over previous
#include <cuda_runtime.h>
#include <cuda_fp16.h>
#include <math.h>
#include <stdint.h>

#define T_SEQ 2048
#define N_EMBD 2048
#define N_HEADS 16
#define N_GROUPS 4
#define HEAD_SIZE 128
#define INTER 5632
#define VOCAB 32000
#define QKV_DIM 3072

// ---------------- scratch ---------------------------------------------------
__device__ float g_x  [T_SEQ * N_EMBD];
__device__ float g_n  [T_SEQ * N_EMBD];
__device__ float g_qkv[T_SEQ * QKV_DIM];
__device__ float g_q  [N_HEADS  * T_SEQ * HEAD_SIZE];
__device__ float g_k  [N_GROUPS * T_SEQ * HEAD_SIZE];
__device__ float g_vT [N_GROUPS * HEAD_SIZE * T_SEQ];
__device__ float g_S  [N_HEADS * T_SEQ * T_SEQ];
__device__ float g_y  [T_SEQ * N_EMBD];
__device__ float g_h1 [T_SEQ * INTER];
__device__ float g_h2 [T_SEQ * INTER];

// ---------------- helpers ---------------------------------------------------
__device__ __forceinline__ uint32_t cvta_smem(const void* p) {
    uint32_t a;
    asm("{.reg .u64 t; cvta.to.shared.u64 t, %1; cvt.u32.u64 %0, t;}" : "=r"(a) : "l"(p));
    return a;
}

__device__ __forceinline__ void mma16(float* d, const uint32_t* a, const uint32_t* b) {
    asm volatile(
        "mma.sync.aligned.m16n8k16.row.col.f32.f16.f16.f32 "
        "{%0,%1,%2,%3}, {%4,%5,%6,%7}, {%8,%9}, {%0,%1,%2,%3};"
        : "+f"(d[0]), "+f"(d[1]), "+f"(d[2]), "+f"(d[3])
        : "r"(a[0]), "r"(a[1]), "r"(a[2]), "r"(a[3]), "r"(b[0]), "r"(b[1]));
}

__device__ __forceinline__ void ldsm4(uint32_t* r, uint32_t addr) {
    asm volatile("ldmatrix.sync.aligned.m8n8.x4.shared.b16 {%0,%1,%2,%3}, [%4];"
        : "=r"(r[0]), "=r"(r[1]), "=r"(r[2]), "=r"(r[3]) : "r"(addr));
}

__device__ __forceinline__ void split4(float4 v, uint2& hi, uint2& lo) {
    __half2 h01 = __floats2half2_rn(v.x, v.y);
    __half2 h23 = __floats2half2_rn(v.z, v.w);
    float2 f01 = __half22float2(h01);
    float2 f23 = __half22float2(h23);
    __half2 l01 = __floats2half2_rn(v.x - f01.x, v.y - f01.y);
    __half2 l23 = __floats2half2_rn(v.z - f23.x, v.w - f23.y);
    hi.x = *(uint32_t*)&h01; hi.y = *(uint32_t*)&h23;
    lo.x = *(uint32_t*)&l01; lo.y = *(uint32_t*)&l23;
}
__device__ __forceinline__ void trunc4(float4 v, uint2& hi) {
    __half2 h01 = __floats2half2_rn(v.x, v.y);
    __half2 h23 = __floats2half2_rn(v.z, v.w);
    hi.x = *(uint32_t*)&h01; hi.y = *(uint32_t*)&h23;
}

// ---------------- fp16 split NT GEMM (mma.sync m16n8k16 + ldmatrix) ---------
// C = A@B^T (+addC). TERMS=3: AhBh+AhBl+AlBh; TERMS=2: AhBh+AlBh; TERMS=1: AhBh.
// mode: 0 plain
//       1 causal S: skip tiles above diagonal, epilogue scale+mask
//       2 causal PV: K clamped at diagonal; pre-pass computes A row sums and
//         scales A rows by 1/(rowsum+1e-8) (linear-attention normalize)
#define BMT 128
#define BNT 128
#define KB  32
#define ROWW 20
#define SUBW (128 * ROWW)

template<int TERMS>
__global__ void __launch_bounds__(256)
gemm_f16(const float* __restrict__ A, int lda, long long sA,
         const float* __restrict__ B, int ldb, long long sB, int bdiv,
         float* C, int ldc, long long sC,
         const float* __restrict__ addC,
         int K, int mode, float scaleC)
{
    constexpr int NA   = (TERMS >= 2) ? 2 : 1;          // A subtiles
    constexpr int NSUB = NA + ((TERMS == 3) ? 2 : 1);   // total subtiles
    constexpr int STGW = NSUB * SUBW;
    extern __shared__ __align__(16) uint32_t smw[];
    const int m0 = blockIdx.x * BMT;
    const int n0 = blockIdx.y * BNT;
    if (mode == 1 && n0 > m0 + BMT - 1) return;
    const int Keff = (mode == 2) ? min(K, m0 + BMT) : K;
    const int KT = Keff / KB;
    const int z = blockIdx.z;
    A += (long long)z * sA;
    B += (long long)(z / bdiv) * sB;
    const long long coff = (long long)z * sC;

    const int tid  = threadIdx.x;
    const int lane = tid & 31;
    const int wid  = tid >> 5;
    const int wm   = (wid & 1) * 64;
    const int wn   = (wid >> 1) * 32;
    const uint32_t sbase = cvta_smem(smw);

    const int aRow  = wm + (lane & 15);
    const int aCol4 = (lane & 16) ? 4 : 0;
    const int bRow  = wn + (lane & 7) + ((lane & 16) ? 8 : 0);
    const int bCol4 = (lane & 8) ? 4 : 0;

    float4 rA[4], rB[4];
    const int lr = tid >> 3;
    const int lc = tid & 7;

    // ---- mode 2: deterministic row-sum pre-pass over A strip ----
    float ascale[4] = {1.f, 1.f, 1.f, 1.f};
    if (mode == 2) {
        float rs[4] = {0.f, 0.f, 0.f, 0.f};
        for (int kt = 0; kt < KT; kt++) {
            #pragma unroll
            for (int it = 0; it < 4; it++) {
                int r = it * 32 + lr;
                float4 v = *(const float4*)(A + (long long)(m0 + r) * lda + kt * KB + lc * 4);
                rs[it] += (v.x + v.y) + (v.z + v.w);
            }
        }
        #pragma unroll
        for (int it = 0; it < 4; it++) {
            #pragma unroll
            for (int o = 1; o < 8; o <<= 1)
                rs[it] += __shfl_xor_sync(0xffffffffu, rs[it], o);
            ascale[it] = 1.f / (rs[it] + 1e-8f);
        }
    }

    auto ldg_tile = [&](int kt) {
        #pragma unroll
        for (int it = 0; it < 4; it++) {
            int r = it * 32 + lr;
            rA[it] = *(const float4*)(A + (long long)(m0 + r) * lda + kt * KB + lc * 4);
            rB[it] = *(const float4*)(B + (long long)(n0 + r) * ldb + kt * KB + lc * 4);
        }
    };
    auto sts_tile = [&](int s) {
        uint32_t* st = smw + s * STGW;
        #pragma unroll
        for (int it = 0; it < 4; it++) {
            int r = it * 32 + lr;
            int w = r * ROWW + lc * 2;
            float4 av = rA[it];
            if (mode == 2) { av.x *= ascale[it]; av.y *= ascale[it]; av.z *= ascale[it]; av.w *= ascale[it]; }
            uint2 hi, lo;
            if (TERMS >= 2) {
                split4(av, hi, lo);
                *(uint2*)(st + w) = hi;
                *(uint2*)(st + SUBW + w) = lo;
            } else {
                trunc4(av, hi);
                *(uint2*)(st + w) = hi;
            }
            if (TERMS == 3) {
                split4(rB[it], hi, lo);
                *(uint2*)(st + NA * SUBW + w) = hi;
                *(uint2*)(st + (NA + 1) * SUBW + w) = lo;
            } else {
                trunc4(rB[it], hi);
                *(uint2*)(st + NA * SUBW + w) = hi;
            }
        }
    };

    float acc[4][4][4];
    #pragma unroll
    for (int a = 0; a < 4; a++)
        #pragma unroll
        for (int b = 0; b < 4; b++)
            #pragma unroll
            for (int c = 0; c < 4; c++) acc[a][b][c] = 0.f;

    ldg_tile(0);
    sts_tile(0);
    if (KT > 1) ldg_tile(1);
    __syncthreads();

    for (int kt = 0; kt < KT; kt++) {
        if (kt + 1 < KT) sts_tile((kt + 1) & 1);
        if (kt + 2 < KT) ldg_tile(kt + 2);

        const uint32_t stAddr = sbase + (uint32_t)((kt & 1) * STGW) * 4u;

        #pragma unroll
        for (int ks = 0; ks < 2; ks++) {
            uint32_t Ah[4][4], Al[4][4], Bh[4][2], Bl[4][2];
            #pragma unroll
            for (int mc = 0; mc < 4; mc++) {
                uint32_t off = stAddr + (uint32_t)(((aRow + mc * 16) * ROWW + aCol4 + ks * 8)) * 4u;
                ldsm4(Ah[mc], off);
                if (TERMS >= 2) ldsm4(Al[mc], off + SUBW * 4u);
            }
            #pragma unroll
            for (int ncp = 0; ncp < 2; ncp++) {
                uint32_t off = stAddr + (uint32_t)((NA * SUBW + (bRow + ncp * 16) * ROWW + bCol4 + ks * 8)) * 4u;
                uint32_t t[4];
                ldsm4(t, off);
                Bh[ncp * 2][0] = t[0]; Bh[ncp * 2][1] = t[1];
                Bh[ncp * 2 + 1][0] = t[2]; Bh[ncp * 2 + 1][1] = t[3];
                if (TERMS == 3) {
                    ldsm4(t, off + SUBW * 4u);
                    Bl[ncp * 2][0] = t[0]; Bl[ncp * 2][1] = t[1];
                    Bl[ncp * 2 + 1][0] = t[2]; Bl[ncp * 2 + 1][1] = t[3];
                }
            }
            #pragma unroll
            for (int mc = 0; mc < 4; mc++)
                #pragma unroll
                for (int nc = 0; nc < 4; nc++) {
                    mma16(acc[mc][nc], Ah[mc], Bh[nc]);
                    if (TERMS == 3) mma16(acc[mc][nc], Ah[mc], Bl[nc]);
                    if (TERMS >= 2) mma16(acc[mc][nc], Al[mc], Bh[nc]);
                }
        }
        __syncthreads();
    }

    // ---- epilogue ----
    #pragma unroll
    for (int mc = 0; mc < 4; mc++)
        #pragma unroll
        for (int nc = 0; nc < 4; nc++) {
            int c0 = n0 + wn + nc * 8 + (lane & 3) * 2;
            #pragma unroll
            for (int rr = 0; rr < 2; rr++) {
                int row = m0 + wm + mc * 16 + (lane >> 2) + rr * 8;
                float v0 = acc[mc][nc][rr * 2] * scaleC;
                float v1 = acc[mc][nc][rr * 2 + 1] * scaleC;
                if (mode == 1) {                 // causal mask
                    if (c0 > row)     v0 = 0.f;
                    if (c0 + 1 > row) v1 = 0.f;
                }
                long long off = coff + (long long)row * ldc + c0;
                if (addC) { v0 += addC[off]; v1 += addC[off + 1]; }
                C[off] = v0;
                C[off + 1] = v1;
            }
        }
}

// ---------------- elementwise kernels ---------------------------------------
__global__ void embed_kernel(const int* __restrict__ idx,
                             const float* __restrict__ wte, float* __restrict__ x)
{
    int t = blockIdx.x;
    const float* src = wte + (long long)idx[t] * N_EMBD;
    float* dst = x + (long long)t * N_EMBD;
    for (int e = threadIdx.x; e < N_EMBD; e += blockDim.x) dst[e] = src[e];
}

__global__ void rmsnorm_kernel(const float* __restrict__ x, const float* __restrict__ w,
                               float* __restrict__ out)
{
    int t = blockIdx.x;
    const float* row = x + (long long)t * N_EMBD;
    float s = 0.f;
    for (int e = threadIdx.x; e < N_EMBD; e += blockDim.x) { float v = row[e]; s += v * v; }
    __shared__ float red[32];
    #pragma unroll
    for (int o = 16; o; o >>= 1) s += __shfl_xor_sync(0xffffffffu, s, o);
    if ((threadIdx.x & 31) == 0) red[threadIdx.x >> 5] = s;
    __syncthreads();
    if (threadIdx.x < 32) {
        float v = (threadIdx.x < (blockDim.x >> 5)) ? red[threadIdx.x] : 0.f;
        #pragma unroll
        for (int o = 16; o; o >>= 1) v += __shfl_xor_sync(0xffffffffu, v, o);
        if (threadIdx.x == 0) red[0] = v;
    }
    __syncthreads();
    float r = rsqrtf(red[0] * (1.f / N_EMBD) + 1e-5f);
    float* dst = out + (long long)t * N_EMBD;
    for (int e = threadIdx.x; e < N_EMBD; e += blockDim.x)
        dst[e] = row[e] * r * w[e];
}

__global__ void qkv_post_kernel(const float* __restrict__ qkv,
                                float* __restrict__ q,
                                float* __restrict__ k,
                                float* __restrict__ vT)
{
    int t = blockIdx.x;
    const float LN_BASE = 9.210340371976184f;
    for (int i = threadIdx.x; i < N_GROUPS * 6 * 64; i += blockDim.x) {
        int j    = i & 63;
        int slot = (i >> 6) % 6;
        int g    = i / (6 * 64);
        const float* src = qkv + (long long)t * QKV_DIM + (g * 6 + slot) * HEAD_SIZE;
        float x1 = src[j];
        float x2 = src[j + 64];
        if (slot < 5) {
            float theta = expf(-(2.f * j / 128.f) * LN_BASE);
            float ang = (float)t * theta;
            float sv, cv;
            sincosf(ang, &sv, &cv);
            float o1 = x1 * cv - x2 * sv;
            float o2 = x1 * sv + x2 * cv;
            o1 = (o1 > 0.f) ? (o1 + 1.f) : expf(o1);
            o2 = (o2 > 0.f) ? (o2 + 1.f) : expf(o2);
            if (slot < 4) {
                int h = g * 4 + slot;
                float* dst = q + ((long long)h * T_SEQ + t) * HEAD_SIZE;
                dst[j] = o1; dst[j + 64] = o2;
            } else {
                float* dst = k + ((long long)g * T_SEQ + t) * HEAD_SIZE;
                dst[j] = o1; dst[j + 64] = o2;
            }
        } else {
            vT[((long long)g * HEAD_SIZE + j) * T_SEQ + t]      = x1;
            vT[((long long)g * HEAD_SIZE + j + 64) * T_SEQ + t] = x2;
        }
    }
}

__global__ void swiglu_kernel(float* __restrict__ a, const float* __restrict__ b)
{
    long long i = (long long)blockIdx.x * blockDim.x + threadIdx.x;
    if (i < (long long)T_SEQ * INTER) {
        float x = a[i];
        float sig = 1.f / (1.f + expf(-x));
        a[i] = x * sig * b[i];
    }
}

// ---------------- orchestration ---------------------------------------------
extern "C" void kernel_launch(void* const* d_in, const int* in_sizes, int n_in,
                              void* d_out, int out_size)
{
    const int*   idx       = (const int*)  d_in[0];
    const float* wte       = (const float*)d_in[1];
    const float* attn_w    = (const float*)d_in[2];
    const float* proj_w    = (const float*)d_in[3];
    const float* w1        = (const float*)d_in[4];
    const float* w2        = (const float*)d_in[5];
    const float* w3        = (const float*)d_in[6];
    const float* norm1_w   = (const float*)d_in[7];
    const float* norm2_w   = (const float*)d_in[8];
    const float* ln_f_w    = (const float*)d_in[9];
    const float* lm_head_w = (const float*)d_in[10];
    float* out = (float*)d_out;

    float *x, *n, *qkv, *q, *k, *vT, *S, *y, *h1, *h2;
    cudaGetSymbolAddress((void**)&x,   g_x);
    cudaGetSymbolAddress((void**)&n,   g_n);
    cudaGetSymbolAddress((void**)&qkv, g_qkv);
    cudaGetSymbolAddress((void**)&q,   g_q);
    cudaGetSymbolAddress((void**)&k,   g_k);
    cudaGetSymbolAddress((void**)&vT,  g_vT);
    cudaGetSymbolAddress((void**)&S,   g_S);
    cudaGetSymbolAddress((void**)&y,   g_y);
    cudaGetSymbolAddress((void**)&h1,  g_h1);
    cudaGetSymbolAddress((void**)&h2,  g_h2);

    const int SMEM3 = 2 * 4 * SUBW * 4;   // 81920 B
    const int SMEM2 = 2 * 3 * SUBW * 4;   // 61440 B
    const int SMEM1 = 2 * 2 * SUBW * 4;   // 40960 B
    cudaFuncSetAttribute(gemm_f16<3>, cudaFuncAttributeMaxDynamicSharedMemorySize, SMEM3);
    cudaFuncSetAttribute(gemm_f16<2>, cudaFuncAttributeMaxDynamicSharedMemorySize, SMEM2);
    cudaFuncSetAttribute(gemm_f16<1>, cudaFuncAttributeMaxDynamicSharedMemorySize, SMEM1);

    const long long TT = (long long)T_SEQ * T_SEQ;
    const long long TH = (long long)T_SEQ * HEAD_SIZE;
    const float SSCALE = 0.08838834764831845f;   // 1/sqrt(128)

    embed_kernel<<<T_SEQ, 256>>>(idx, wte, x);

    for (int l = 0; l < 2; l++) {
        const float* aw  = attn_w + (long long)l * QKV_DIM * N_EMBD;
        const float* pw  = proj_w + (long long)l * N_EMBD * N_EMBD;
        const float* w1l = w1 + (long long)l * INTER * N_EMBD;
        const float* w2l = w2 + (long long)l * INTER * N_EMBD;
        const float* w3l = w3 + (long long)l * N_EMBD * INTER;

        rmsnorm_kernel<<<T_SEQ, 256>>>(x, norm1_w + l * N_EMBD, n);

        // qkv = n1 @ attn_w^T  (3-term)
        gemm_f16<3><<<dim3(T_SEQ / BMT, QKV_DIM / BNT, 1), 256, SMEM3>>>(
            n, N_EMBD, 0, aw, N_EMBD, 0, 1,
            qkv, QKV_DIM, 0, nullptr, N_EMBD, 0, 1.f);

        qkv_post_kernel<<<T_SEQ, 512>>>(qkv, q, k, vT);

        // S[h] = mask(q[h] @ k[g]^T * scale)   (3-term, fused mask+scale)
        gemm_f16<3><<<dim3(T_SEQ / BMT, T_SEQ / BNT, N_HEADS), 256, SMEM3>>>(
            q, HEAD_SIZE, TH, k, HEAD_SIZE, TH, 4,
            S, T_SEQ, TT, nullptr, HEAD_SIZE, 1, SSCALE);

        // y[:, h] = (S/rowsum)[h] @ vT[g]^T   (3-term, fused normalize)
        gemm_f16<3><<<dim3(T_SEQ / BMT, HEAD_SIZE / BNT, N_HEADS), 256, SMEM3>>>(
            S, T_SEQ, TT, vT, T_SEQ, (long long)HEAD_SIZE * T_SEQ, 4,
            y, N_EMBD, HEAD_SIZE, nullptr, T_SEQ, 2, 1.f);

        // x = x + y @ proj_w^T  (3-term)
        gemm_f16<3><<<dim3(T_SEQ / BMT, N_EMBD / BNT, 1), 256, SMEM3>>>(
            y, N_EMBD, 0, pw, N_EMBD, 0, 1,
            x, N_EMBD, 0, x, N_EMBD, 0, 1.f);

        rmsnorm_kernel<<<T_SEQ, 256>>>(x, norm2_w + l * N_EMBD, n);

        // MLP: 2-term
        gemm_f16<2><<<dim3(T_SEQ / BMT, INTER / BNT, 1), 256, SMEM2>>>(
            n, N_EMBD, 0, w1l, N_EMBD, 0, 1,
            h1, INTER, 0, nullptr, N_EMBD, 0, 1.f);
        gemm_f16<2><<<dim3(T_SEQ / BMT, INTER / BNT, 1), 256, SMEM2>>>(
            n, N_EMBD, 0, w2l, N_EMBD, 0, 1,
            h2, INTER, 0, nullptr, N_EMBD, 0, 1.f);

        swiglu_kernel<<<(T_SEQ * INTER) / 256, 256>>>(h1, h2);

        gemm_f16<2><<<dim3(T_SEQ / BMT, N_EMBD / BNT, 1), 256, SMEM2>>>(
            h1, INTER, 0, w3l, INTER, 0, 1,
            x, N_EMBD, 0, x, INTER, 0, 1.f);
    }

    rmsnorm_kernel<<<T_SEQ, 256>>>(x, ln_f_w, n);
    // lm_head: 1-term fp16
    gemm_f16<1><<<dim3(T_SEQ / BMT, VOCAB / BNT, 1), 256, SMEM1>>>(
        n, N_EMBD, 0, lm_head_w, N_EMBD, 0, 1,
        out, VOCAB, 0, nullptr, N_EMBD, 0, 1.f);
}